// round 1
// baseline (speedup 1.0000x reference)
#include <cuda_runtime.h>
#include <cstdint>

// ---------------- constants ----------------
#define B_SZ   16
#define LINES  128
#define WPL    32
#define NLINE  (B_SZ*LINES)          // 2048
#define NTOK   (NLINE*WPL)           // 65536
#define EMB_D  300
#define AD     400
#define HEADS  8
#define DPH    50
#define NCAT   1200                  // q|k|v concatenated
#define INV_SQRT50 0.14142135623730951f
#define NEGPEN 1e7f

// ---------------- scratch (device globals; no allocation allowed) ----------------
__device__ float g_wqkv[(long)NTOK * NCAT];    // [65536][1200]  q|k|v word proj
__device__ float g_lineE[NLINE * AD];          // [2048][400]
__device__ float g_lqkv[NLINE * NCAT];         // [2048][1200]   line proj q|k|v
__device__ float g_docE[B_SZ * AD];            // [16][400]

// =====================================================================
// Fused (optional gather) GEMM + bias + ELU:
//   out[m][c] = elu( A[m][:] . W_{c/400}[:, c%400] + b_{c/400}[c%400] )
// TILE 128x128, BK=20, 256 threads, 8x8 register tile.
// =====================================================================
#define TM 128
#define TN 128
#define BK 20

template<bool GATHER>
__global__ __launch_bounds__(256, 2)
void proj_kernel(const float* __restrict__ Asrc,   // GATHER: emb[VOCAB][K]; else dense [M][K]
                 const int*   __restrict__ tok,    // GATHER: token ids [M]
                 const float* __restrict__ W0, const float* __restrict__ W1, const float* __restrict__ W2,
                 const float* __restrict__ Bb0, const float* __restrict__ Bb1, const float* __restrict__ Bb2,
                 float* __restrict__ out, int K)
{
    __shared__ __align__(16) float As[BK][TM];
    __shared__ __align__(16) float Bs[BK][TN];
    __shared__ int toks[TM];

    const int tid  = threadIdx.x;
    const int row0 = blockIdx.x * TM;
    const int col0 = blockIdx.y * TN;

    if (GATHER) {
        if (tid < TM) toks[tid] = tok[row0 + tid];
    }
    __syncthreads();

    float acc[8][8];
    #pragma unroll
    for (int i = 0; i < 8; i++)
        #pragma unroll
        for (int j = 0; j < 8; j++) acc[i][j] = 0.f;

    const int tx = tid & 15;    // col group
    const int ty = tid >> 4;    // row group

    const int nK = K / BK;      // 300->15, 400->20
    for (int kt = 0; kt < nK; kt++) {
        const int k0 = kt * BK;
        // ---- load A tile (transposed into As[k][m]) via float4 along k ----
        for (int i = tid; i < TM * (BK / 4); i += 256) {
            int m  = i / (BK / 4);
            int kq = i % (BK / 4);
            const float* ptr;
            if (GATHER) ptr = Asrc + (long)toks[m] * K + k0 + kq * 4;
            else        ptr = Asrc + (long)(row0 + m) * K + k0 + kq * 4;
            float4 v = *reinterpret_cast<const float4*>(ptr);
            As[kq * 4 + 0][m] = v.x;
            As[kq * 4 + 1][m] = v.y;
            As[kq * 4 + 2][m] = v.z;
            As[kq * 4 + 3][m] = v.w;
        }
        // ---- load B tile Bs[k][n] (selecting among the 3 weight mats) ----
        for (int i = tid; i < BK * (TN / 4); i += 256) {
            int k  = i / (TN / 4);
            int nq = i % (TN / 4);
            int c  = col0 + nq * 4;           // multiple of 4 -> never crosses a 400 boundary
            float4 v = make_float4(0.f, 0.f, 0.f, 0.f);
            if (c < NCAT) {
                const float* W = (c < AD) ? W0 : (c < 2 * AD ? W1 : W2);
                int lc = c - (c < AD ? 0 : (c < 2 * AD ? AD : 2 * AD));
                v = *reinterpret_cast<const float4*>(W + (long)(k0 + k) * AD + lc);
            }
            *reinterpret_cast<float4*>(&Bs[k][nq * 4]) = v;
        }
        __syncthreads();
        #pragma unroll
        for (int kk = 0; kk < BK; kk++) {
            float4 a0 = *reinterpret_cast<const float4*>(&As[kk][ty * 4]);
            float4 a1 = *reinterpret_cast<const float4*>(&As[kk][64 + ty * 4]);
            float4 b0 = *reinterpret_cast<const float4*>(&Bs[kk][tx * 4]);
            float4 b1 = *reinterpret_cast<const float4*>(&Bs[kk][64 + tx * 4]);
            float ar[8] = {a0.x, a0.y, a0.z, a0.w, a1.x, a1.y, a1.z, a1.w};
            float br[8] = {b0.x, b0.y, b0.z, b0.w, b1.x, b1.y, b1.z, b1.w};
            #pragma unroll
            for (int i = 0; i < 8; i++)
                #pragma unroll
                for (int j = 0; j < 8; j++)
                    acc[i][j] = fmaf(ar[i], br[j], acc[i][j]);
        }
        __syncthreads();
    }

    // ---- epilogue: + bias, ELU, store ----
    #pragma unroll
    for (int jj = 0; jj < 8; jj++) {
        int c = col0 + ((jj < 4) ? (tx * 4 + jj) : (64 + tx * 4 + (jj - 4)));
        if (c >= NCAT) continue;
        const float* Bb = (c < AD) ? Bb0 : (c < 2 * AD ? Bb1 : Bb2);
        float bias = Bb[c - (c < AD ? 0 : (c < 2 * AD ? AD : 2 * AD))];
        #pragma unroll
        for (int ii = 0; ii < 8; ii++) {
            int r = row0 + ((ii < 4) ? (ty * 4 + ii) : (64 + ty * 4 + (ii - 4)));
            float x = acc[ii][jj] + bias;
            out[(long)r * NCAT + c] = (x > 0.f) ? x : expm1f(x);
        }
    }
}

// =====================================================================
// Word-level attention + target attention.
// One block per (line, head). 128 threads.
// Produces line_e[line][h*50+d]. Empty lines -> exact zeros (watt==0).
// =====================================================================
__global__ __launch_bounds__(128)
void watt_kernel(const int* __restrict__ docs, const float* __restrict__ w_tgt,
                 float* __restrict__ lineE)
{
    const int line = blockIdx.x;
    const int h    = blockIdx.y;
    const int tid  = threadIdx.x;

    __shared__ float q[WPL * DPH], k[WPL * DPH], v[WPL * DPH];
    __shared__ float ws[WPL * 33];
    __shared__ float watt[WPL * DPH];
    __shared__ float tw[WPL];
    __shared__ int   msk[WPL];

    if (tid < WPL) msk[tid] = (docs[line * WPL + tid] != 0);
    for (int i = tid; i < WPL * DPH; i += 128) {
        int w = i / DPH, d = i % DPH;
        long base = (long)(line * WPL + w) * NCAT + h * DPH + d;
        q[i] = g_wqkv[base];
        k[i] = g_wqkv[base + AD];
        v[i] = g_wqkv[base + 2 * AD];
    }
    __syncthreads();

    // scores: each thread a 2x4 tile of the 32x32 score matrix
    {
        int i0 = (tid >> 3) * 2;
        int j0 = (tid & 7) * 4;
        float s0[4] = {0.f, 0.f, 0.f, 0.f};
        float s1[4] = {0.f, 0.f, 0.f, 0.f};
        for (int d = 0; d < DPH; d++) {
            float qa = q[i0 * DPH + d];
            float qb = q[(i0 + 1) * DPH + d];
            #pragma unroll
            for (int jj = 0; jj < 4; jj++) {
                float kv = k[(j0 + jj) * DPH + d];
                s0[jj] = fmaf(qa, kv, s0[jj]);
                s1[jj] = fmaf(qb, kv, s1[jj]);
            }
        }
        #pragma unroll
        for (int jj = 0; jj < 4; jj++) {
            float m = msk[j0 + jj] ? 0.f : NEGPEN;
            ws[i0 * 33 + j0 + jj]       = s0[jj] * INV_SQRT50 - m;
            ws[(i0 + 1) * 33 + j0 + jj] = s1[jj] * INV_SQRT50 - m;
        }
    }
    __syncthreads();

    // row softmax (+ query-axis mask => zeroed rows)
    {
        int wi = tid >> 5, ln = tid & 31;
        for (int r = wi; r < WPL; r += 4) {
            float x = ws[r * 33 + ln];
            float mx = x;
            #pragma unroll
            for (int o = 16; o; o >>= 1) mx = fmaxf(mx, __shfl_xor_sync(~0u, mx, o));
            float e = __expf(x - mx);
            float sm = e;
            #pragma unroll
            for (int o = 16; o; o >>= 1) sm += __shfl_xor_sync(~0u, sm, o);
            float wv = e / sm;
            if (!msk[r]) wv = 0.f;
            ws[r * 33 + ln] = wv;
        }
    }
    __syncthreads();

    // watt = w @ v  (2-row register tile)
    for (int u = tid; u < (WPL / 2) * DPH; u += 128) {
        int ip = u / DPH, d = u % DPH;
        int i0 = ip * 2;
        float a0 = 0.f, a1 = 0.f;
        for (int j = 0; j < WPL; j++) {
            float vv = v[j * DPH + d];
            a0 = fmaf(ws[i0 * 33 + j], vv, a0);
            a1 = fmaf(ws[(i0 + 1) * 33 + j], vv, a1);
        }
        watt[i0 * DPH + d] = a0;
        watt[(i0 + 1) * DPH + d] = a1;
    }
    __syncthreads();

    // target attention: scores over keys (wk), softmax, values = watt
    if (tid < WPL) {
        int j = tid;
        float s = 0.f;
        for (int d = 0; d < DPH; d++)
            s = fmaf(w_tgt[h * DPH + d], k[j * DPH + d], s);
        s *= INV_SQRT50;
        if (!msk[j]) s -= NEGPEN;
        float mx = s;
        #pragma unroll
        for (int o = 16; o; o >>= 1) mx = fmaxf(mx, __shfl_xor_sync(~0u, mx, o));
        float e = __expf(s - mx);
        float sm = e;
        #pragma unroll
        for (int o = 16; o; o >>= 1) sm += __shfl_xor_sync(~0u, sm, o);
        tw[j] = e / sm;
    }
    __syncthreads();

    if (tid < DPH) {
        int d = tid;
        float a = 0.f;
        for (int j = 0; j < WPL; j++) a = fmaf(tw[j], watt[j * DPH + d], a);
        lineE[(long)line * AD + h * DPH + d] = a;
    }
}

// =====================================================================
// Line-level attention + doc target attention.
// One block per (doc, head). 256 threads. Dynamic smem (~168 KB).
// =====================================================================
#define LA_Q  0
#define LA_K  (LINES * DPH)
#define LA_V  (2 * LINES * DPH)
#define LA_A  (3 * LINES * DPH)
#define LA_S  (4 * LINES * DPH)           // scores [128][129]
#define LA_FLOATS (LA_S + LINES * 129)    // 42112 floats
#define LA_SMEM_BYTES (LA_FLOATS * 4)     // 168448 B

__global__ __launch_bounds__(256)
void latt_kernel(const int* __restrict__ docs, const float* __restrict__ l_tgt,
                 float* __restrict__ docE)
{
    extern __shared__ float sm[];
    __shared__ int   mskL[LINES];
    __shared__ float ts[LINES];

    const int doc = blockIdx.x;
    const int h   = blockIdx.y;
    const int tid = threadIdx.x;

    if (tid < LINES) {
        int any = 0;
        const int* p = docs + (long)(doc * LINES + tid) * WPL;
        for (int w = 0; w < WPL; w++) any |= p[w];
        mskL[tid] = (any != 0);
    }
    for (int i = tid; i < LINES * DPH; i += 256) {
        int l = i / DPH, d = i % DPH;
        long base = (long)(doc * LINES + l) * NCAT + h * DPH + d;
        sm[LA_Q + i] = g_lqkv[base];
        sm[LA_K + i] = g_lqkv[base + AD];
        sm[LA_V + i] = g_lqkv[base + 2 * AD];
    }
    __syncthreads();

    // scores: 2x4 register tiles over 128x128
    for (int u = tid; u < (LINES / 2) * (LINES / 4); u += 256) {
        int ip = u >> 5;            // 0..63
        int jq = u & 31;
        int i0 = ip * 2, j0 = jq * 4;
        float s0[4] = {0.f, 0.f, 0.f, 0.f};
        float s1[4] = {0.f, 0.f, 0.f, 0.f};
        for (int d = 0; d < DPH; d++) {
            float qa = sm[LA_Q + i0 * DPH + d];
            float qb = sm[LA_Q + (i0 + 1) * DPH + d];
            #pragma unroll
            for (int jj = 0; jj < 4; jj++) {
                float kv = sm[LA_K + (j0 + jj) * DPH + d];
                s0[jj] = fmaf(qa, kv, s0[jj]);
                s1[jj] = fmaf(qb, kv, s1[jj]);
            }
        }
        #pragma unroll
        for (int jj = 0; jj < 4; jj++) {
            float m = mskL[j0 + jj] ? 0.f : NEGPEN;
            sm[LA_S + i0 * 129 + j0 + jj]       = s0[jj] * INV_SQRT50 - m;
            sm[LA_S + (i0 + 1) * 129 + j0 + jj] = s1[jj] * INV_SQRT50 - m;
        }
    }
    __syncthreads();

    // softmax per row (+ query mask)
    {
        int wi = tid >> 5, ln = tid & 31;
        for (int r = wi; r < LINES; r += 8) {
            float x0 = sm[LA_S + r * 129 + ln];
            float x1 = sm[LA_S + r * 129 + ln + 32];
            float x2 = sm[LA_S + r * 129 + ln + 64];
            float x3 = sm[LA_S + r * 129 + ln + 96];
            float mx = fmaxf(fmaxf(x0, x1), fmaxf(x2, x3));
            #pragma unroll
            for (int o = 16; o; o >>= 1) mx = fmaxf(mx, __shfl_xor_sync(~0u, mx, o));
            float e0 = __expf(x0 - mx), e1 = __expf(x1 - mx);
            float e2 = __expf(x2 - mx), e3 = __expf(x3 - mx);
            float smv = e0 + e1 + e2 + e3;
            #pragma unroll
            for (int o = 16; o; o >>= 1) smv += __shfl_xor_sync(~0u, smv, o);
            float inv = (mskL[r] ? 1.f : 0.f) / smv;
            sm[LA_S + r * 129 + ln]      = e0 * inv;
            sm[LA_S + r * 129 + ln + 32] = e1 * inv;
            sm[LA_S + r * 129 + ln + 64] = e2 * inv;
            sm[LA_S + r * 129 + ln + 96] = e3 * inv;
        }
    }
    __syncthreads();

    // latt = w @ v  (2-row tiles)
    for (int u = tid; u < (LINES / 2) * DPH; u += 256) {
        int ip = u / DPH, d = u % DPH;
        int i0 = ip * 2;
        float a0 = 0.f, a1 = 0.f;
        for (int j = 0; j < LINES; j++) {
            float vv = sm[LA_V + j * DPH + d];
            a0 = fmaf(sm[LA_S + i0 * 129 + j], vv, a0);
            a1 = fmaf(sm[LA_S + (i0 + 1) * 129 + j], vv, a1);
        }
        sm[LA_A + i0 * DPH + d] = a0;
        sm[LA_A + (i0 + 1) * DPH + d] = a1;
    }
    __syncthreads();

    // doc target attention: scores over lk, values = latt
    if (tid < LINES) {
        int j = tid;
        float s = 0.f;
        for (int d = 0; d < DPH; d++)
            s = fmaf(l_tgt[h * DPH + d], sm[LA_K + j * DPH + d], s);
        s *= INV_SQRT50;
        if (!mskL[j]) s -= NEGPEN;
        ts[j] = s;
    }
    __syncthreads();
    if (tid < 32) {
        int ln = tid;
        float x0 = ts[ln], x1 = ts[ln + 32], x2 = ts[ln + 64], x3 = ts[ln + 96];
        float mx = fmaxf(fmaxf(x0, x1), fmaxf(x2, x3));
        #pragma unroll
        for (int o = 16; o; o >>= 1) mx = fmaxf(mx, __shfl_xor_sync(~0u, mx, o));
        float e0 = __expf(x0 - mx), e1 = __expf(x1 - mx);
        float e2 = __expf(x2 - mx), e3 = __expf(x3 - mx);
        float smv = e0 + e1 + e2 + e3;
        #pragma unroll
        for (int o = 16; o; o >>= 1) smv += __shfl_xor_sync(~0u, smv, o);
        float inv = 1.f / smv;
        ts[ln] = e0 * inv; ts[ln + 32] = e1 * inv;
        ts[ln + 64] = e2 * inv; ts[ln + 96] = e3 * inv;
    }
    __syncthreads();
    if (tid < DPH) {
        int d = tid;
        float a = 0.f;
        for (int j = 0; j < LINES; j++) a = fmaf(ts[j], sm[LA_A + j * DPH + d], a);
        docE[(long)doc * AD + h * DPH + d] = a;
    }
}

// =====================================================================
// Final FC: logits = [doc_e @ fc1 + b1 | doc_e @ fc2 + b2]  -> [16][582]
// =====================================================================
__global__ __launch_bounds__(608)
void fc_kernel(const float* __restrict__ fc1w, const float* __restrict__ fc1b,
               const float* __restrict__ fc2w, const float* __restrict__ fc2b,
               float* __restrict__ out)
{
    const int b = blockIdx.x;
    const int tid = threadIdx.x;
    __shared__ float de[AD];
    for (int i = tid; i < AD; i += 608) de[i] = g_docE[b * AD + i];
    __syncthreads();
    if (tid < 582) {
        float a;
        if (tid < 70) {
            a = fc1b[tid];
            for (int kk = 0; kk < AD; kk++) a = fmaf(de[kk], fc1w[kk * 70 + tid], a);
        } else {
            int c = tid - 70;
            a = fc2b[c];
            for (int kk = 0; kk < AD; kk++) a = fmaf(de[kk], fc2w[kk * 512 + c], a);
        }
        out[b * 582 + tid] = a;
    }
}

// =====================================================================
extern "C" void kernel_launch(void* const* d_in, const int* in_sizes, int n_in,
                              void* d_out, int out_size)
{
    const int*   docs  = (const int*)  d_in[0];
    const float* emb   = (const float*)d_in[1];
    const float* wq_w  = (const float*)d_in[2];
    const float* wq_b  = (const float*)d_in[3];
    const float* wk_w  = (const float*)d_in[4];
    const float* wk_b  = (const float*)d_in[5];
    const float* wv_w  = (const float*)d_in[6];
    const float* wv_b  = (const float*)d_in[7];
    const float* w_tgt = (const float*)d_in[8];
    const float* lq_w  = (const float*)d_in[9];
    const float* lq_b  = (const float*)d_in[10];
    const float* lk_w  = (const float*)d_in[11];
    const float* lk_b  = (const float*)d_in[12];
    const float* lv_w  = (const float*)d_in[13];
    const float* lv_b  = (const float*)d_in[14];
    const float* l_tgt = (const float*)d_in[15];
    const float* fc1_w = (const float*)d_in[16];
    const float* fc1_b = (const float*)d_in[17];
    const float* fc2_w = (const float*)d_in[18];
    const float* fc2_b = (const float*)d_in[19];
    float* out = (float*)d_out;

    float *wqkv, *lineE, *lqkv, *docE;
    cudaGetSymbolAddress((void**)&wqkv,  g_wqkv);
    cudaGetSymbolAddress((void**)&lineE, g_lineE);
    cudaGetSymbolAddress((void**)&lqkv,  g_lqkv);
    cudaGetSymbolAddress((void**)&docE,  g_docE);

    // 1) word projections (gather emb + GEMM + ELU): [65536,300]x[300,1200]
    proj_kernel<true><<<dim3(NTOK / TM, 10), 256>>>(
        emb, docs, wq_w, wk_w, wv_w, wq_b, wk_b, wv_b, wqkv, EMB_D);

    // 2) word attention + target attention -> line_e [2048,400]
    watt_kernel<<<dim3(NLINE, HEADS), 128>>>(docs, w_tgt, lineE);

    // 3) line projections: [2048,400]x[400,1200]
    proj_kernel<false><<<dim3(NLINE / TM, 10), 256>>>(
        lineE, nullptr, lq_w, lk_w, lv_w, lq_b, lk_b, lv_b, lqkv, AD);

    // 4) line attention + doc target attention -> doc_e [16,400]
    cudaFuncSetAttribute(latt_kernel, cudaFuncAttributeMaxDynamicSharedMemorySize,
                         LA_SMEM_BYTES);
    latt_kernel<<<dim3(B_SZ, HEADS), 256, LA_SMEM_BYTES>>>(docs, l_tgt, docE);

    // 5) final FC -> [16,582]
    fc_kernel<<<B_SZ, 608>>>(fc1_w, fc1_b, fc2_w, fc2_b, out);
}

// round 3
// speedup vs baseline: 1.4194x; 1.4194x over previous
#include <cuda_runtime.h>
#include <cuda_fp16.h>
#include <cstdint>

// ---------------- constants ----------------
#define B_SZ   16
#define LINES  128
#define WPL    32
#define NLINE  (B_SZ*LINES)          // 2048
#define NTOK   (NLINE*WPL)           // 65536
#define EMB_D  300
#define AD     400
#define HEADS  8
#define DPH    50
#define NCAT   1200                  // q|k|v concatenated
#define INV_SQRT50 0.14142135623730951f
#define NEGPEN 1e7f

// GEMM tiling
#define KPAD    320
#define APITCH  328              // half elements per A row (656B -> conflict-free)
#define NT      80               // N tile
#define NTILES  15               // 1200/80
#define KC      64               // K chunk
#define NCHUNK  5                // 320/64
#define TOTCH   (NTILES*NCHUNK)  // 75
#define BPITCH  72               // half elements per B row (144B)
#define BBUF    (NT*BPITCH)      // 5760 halves per (buf,split)

// ---------------- scratch (device globals; no allocation allowed) ----------------
__device__ float g_wqkv[(long)NTOK * NCAT];    // [65536][1200]
__device__ float g_lineE[NLINE * AD];          // [2048][400]
__device__ float g_lqkv[NLINE * NCAT];         // [2048][1200]
__device__ float g_docE[B_SZ * AD];            // [16][400]
__device__ __align__(16) __half g_Bhi[NCAT * KPAD];  // [1200][320] K-major
__device__ __align__(16) __half g_Blo[NCAT * KPAD];

// ---------------- small PTX helpers (baseline ISA only) ----------------
__device__ __forceinline__ void cp16(void* dst, const void* src) {
    uint32_t d = (uint32_t)__cvta_generic_to_shared(dst);
    asm volatile("cp.async.ca.shared.global [%0], [%1], 16;" :: "r"(d), "l"(src));
}
__device__ __forceinline__ void cp_commit() {
    asm volatile("cp.async.commit_group;" ::: "memory");
}
template<int N>
__device__ __forceinline__ void cp_wait() {
    asm volatile("cp.async.wait_group %0;" :: "n"(N) : "memory");
}
__device__ __forceinline__ void mma16816(float* c, const uint32_t* a, const uint32_t* b) {
    asm volatile("mma.sync.aligned.m16n8k16.row.col.f32.f16.f16.f32 "
        "{%0,%1,%2,%3}, {%4,%5,%6,%7}, {%8,%9}, {%0,%1,%2,%3};"
        : "+f"(c[0]), "+f"(c[1]), "+f"(c[2]), "+f"(c[3])
        : "r"(a[0]), "r"(a[1]), "r"(a[2]), "r"(a[3]), "r"(b[0]), "r"(b[1]));
}
__device__ __forceinline__ uint32_t ld32s(const __half* p) {
    return *reinterpret_cast<const uint32_t*>(p);
}

// =====================================================================
// Prep: split W [300][400]x3 -> g_Bhi/g_Blo [1200 n][320 k] fp16 (K padded w/ 0)
// =====================================================================
__global__ __launch_bounds__(256)
void splitB_kernel(const float* __restrict__ W0, const float* __restrict__ W1,
                   const float* __restrict__ W2)
{
    int idx = blockIdx.x * 256 + threadIdx.x;    // over 1200*160
    if (idx >= NCAT * (KPAD / 2)) return;
    int n  = idx / (KPAD / 2);
    int k0 = (idx % (KPAD / 2)) * 2;
    const float* W = (n < AD) ? W0 : (n < 2 * AD ? W1 : W2);
    int lc = (n < AD) ? n : (n < 2 * AD ? n - AD : n - 2 * AD);
    float x0 = (k0     < EMB_D) ? W[k0 * AD + lc]       : 0.f;
    float x1 = (k0 + 1 < EMB_D) ? W[(k0 + 1) * AD + lc] : 0.f;
    __half h0 = __float2half(x0), h1 = __float2half(x1);
    __half l0 = __float2half(x0 - __half2float(h0));
    __half l1 = __float2half(x1 - __half2float(h1));
    *reinterpret_cast<__half2*>(g_Bhi + n * KPAD + k0) = __halves2half2(h0, h1);
    *reinterpret_cast<__half2*>(g_Blo + n * KPAD + k0) = __halves2half2(l0, l1);
}

// =====================================================================
// Word projection GEMM via mma.sync fp16 hi/lo 3-term:
//   out[65536][1200] = elu(gather(emb,docs) @ [Wq|Wk|Wv] + bias)
// 512 CTAs x 256 thr. A tile resident (hi+lo), B cp.async double-buffered.
// =====================================================================
#define PROJ_SMEM ((2 * 128 * APITCH + 2 * 2 * BBUF) * 2)   // 214016 B

__global__ __launch_bounds__(256, 1)
void proj_mma_kernel(const int* __restrict__ docs, const float* __restrict__ emb,
                     const float* __restrict__ Bb0, const float* __restrict__ Bb1,
                     const float* __restrict__ Bb2,
                     float* __restrict__ out)
{
    extern __shared__ __half sh[];
    __half* sAhi = sh;
    __half* sAlo = sAhi + 128 * APITCH;
    __half* sB   = sAlo + 128 * APITCH;     // [2 buf][2 split][NT*BPITCH]
    __shared__ int s_tok[128];

    const int tid  = threadIdx.x;
    const int wid  = tid >> 5;
    const int lane = tid & 31;
    const int g4 = lane >> 2;               // 0..7
    const int l4 = lane & 3;                // 0..3
    const int wm = wid >> 1;                // 0..3 (M slab of 32)
    const int wn = wid & 1;                 // 0..1 (N slab of 40)

    if (tid < 128) s_tok[tid] = docs[blockIdx.x * 128 + tid];
    __syncthreads();

    // ---- gather + hi/lo split A into smem ----
    for (int idx = tid; idx < 128 * (KPAD / 2); idx += 256) {
        int m  = idx / (KPAD / 2);
        int k0 = (idx % (KPAD / 2)) * 2;
        float x0 = 0.f, x1 = 0.f;
        if (k0 < EMB_D) {
            float2 v = *reinterpret_cast<const float2*>(emb + (long)s_tok[m] * EMB_D + k0);
            x0 = v.x; x1 = v.y;
        }
        __half h0 = __float2half(x0), h1 = __float2half(x1);
        __half l0 = __float2half(x0 - __half2float(h0));
        __half l1 = __float2half(x1 - __half2float(h1));
        *reinterpret_cast<__half2*>(sAhi + m * APITCH + k0) = __halves2half2(h0, h1);
        *reinterpret_cast<__half2*>(sAlo + m * APITCH + k0) = __halves2half2(l0, l1);
    }

    // ---- B prefetch lambda-ish ----
    auto prefetchB = [&](int g) {
        int nt2 = g / NCHUNK, kc2 = g % NCHUNK, buf = g & 1;
        int colbase = nt2 * NT;
        #pragma unroll
        for (int it = 0; it < 5; it++) {
            int idx = tid + it * 256;          // 0..1279
            int split = idx / 640;
            int rem   = idx % 640;
            int n   = rem >> 3;
            int seg = rem & 7;
            const __half* src = (split ? g_Blo : g_Bhi)
                              + (long)(colbase + n) * KPAD + kc2 * KC + seg * 8;
            __half* dst = sB + (buf * 2 + split) * BBUF + n * BPITCH + seg * 8;
            cp16(dst, src);
        }
    };

    prefetchB(0);
    cp_commit();
    __syncthreads();   // A tile ready

    const __half* pAh = sAhi + (wm * 32 + g4) * APITCH;
    const __half* pAl = sAlo + (wm * 32 + g4) * APITCH;

    for (int nt = 0; nt < NTILES; nt++) {
        float acc[2][5][4];
        #pragma unroll
        for (int mi = 0; mi < 2; mi++)
            #pragma unroll
            for (int ni = 0; ni < 5; ni++)
                #pragma unroll
                for (int r = 0; r < 4; r++) acc[mi][ni][r] = 0.f;

        for (int kc = 0; kc < NCHUNK; kc++) {
            const int g = nt * NCHUNK + kc;
            if (g + 1 < TOTCH) { prefetchB(g + 1); cp_commit(); cp_wait<1>(); }
            else               { cp_wait<0>(); }
            __syncthreads();

            const int buf = g & 1;
            const __half* pBh = sB + (buf * 2 + 0) * BBUF + (wn * 40 + g4) * BPITCH;
            const __half* pBl = sB + (buf * 2 + 1) * BBUF + (wn * 40 + g4) * BPITCH;

            #pragma unroll
            for (int ks = 0; ks < 4; ks++) {
                const int kA = kc * KC + ks * 16 + l4 * 2;
                uint32_t ah[2][4], al[2][4];
                #pragma unroll
                for (int mi = 0; mi < 2; mi++) {
                    const __half* p0 = pAh + mi * (16 * APITCH);
                    const __half* p1 = pAl + mi * (16 * APITCH);
                    ah[mi][0] = ld32s(p0 + kA);
                    ah[mi][1] = ld32s(p0 + 8 * APITCH + kA);
                    ah[mi][2] = ld32s(p0 + kA + 8);
                    ah[mi][3] = ld32s(p0 + 8 * APITCH + kA + 8);
                    al[mi][0] = ld32s(p1 + kA);
                    al[mi][1] = ld32s(p1 + 8 * APITCH + kA);
                    al[mi][2] = ld32s(p1 + kA + 8);
                    al[mi][3] = ld32s(p1 + 8 * APITCH + kA + 8);
                }
                uint32_t bh[5][2], bl[5][2];
                const int kk = ks * 16 + l4 * 2;
                #pragma unroll
                for (int ni = 0; ni < 5; ni++) {
                    bh[ni][0] = ld32s(pBh + ni * (8 * BPITCH) + kk);
                    bh[ni][1] = ld32s(pBh + ni * (8 * BPITCH) + kk + 8);
                    bl[ni][0] = ld32s(pBl + ni * (8 * BPITCH) + kk);
                    bl[ni][1] = ld32s(pBl + ni * (8 * BPITCH) + kk + 8);
                }
                #pragma unroll
                for (int mi = 0; mi < 2; mi++)
                    #pragma unroll
                    for (int ni = 0; ni < 5; ni++) {
                        mma16816(acc[mi][ni], ah[mi], bh[ni]);
                        mma16816(acc[mi][ni], ah[mi], bl[ni]);
                        mma16816(acc[mi][ni], al[mi], bh[ni]);
                    }
            }
            __syncthreads();
        }

        // ---- epilogue: bias + ELU + store ----
        const float* Bb = (nt < 5) ? Bb0 : (nt < 10 ? Bb1 : Bb2);
        const int cb = nt * NT - ((nt < 5) ? 0 : (nt < 10 ? AD : 2 * AD));
        #pragma unroll
        for (int mi = 0; mi < 2; mi++) {
            #pragma unroll
            for (int r01 = 0; r01 < 2; r01++) {
                const long row = (long)blockIdx.x * 128 + wm * 32 + mi * 16 + g4 + r01 * 8;
                #pragma unroll
                for (int ni = 0; ni < 5; ni++) {
                    int lc = cb + wn * 40 + ni * 8 + l4 * 2;
                    float x0 = acc[mi][ni][r01 * 2 + 0] + Bb[lc];
                    float x1 = acc[mi][ni][r01 * 2 + 1] + Bb[lc + 1];
                    float2 o;
                    o.x = (x0 > 0.f) ? x0 : expm1f(x0);
                    o.y = (x1 > 0.f) ? x1 : expm1f(x1);
                    int col = nt * NT + wn * 40 + ni * 8 + l4 * 2;
                    *reinterpret_cast<float2*>(out + row * NCAT + col) = o;
                }
            }
        }
    }
}

// =====================================================================
// FFMA GEMM + bias + ELU (small line projection)
// =====================================================================
#define TM 128
#define TN 128
#define BK 20

__global__ __launch_bounds__(256, 2)
void proj_kernel(const float* __restrict__ Asrc,
                 const float* __restrict__ W0, const float* __restrict__ W1, const float* __restrict__ W2,
                 const float* __restrict__ Bb0, const float* __restrict__ Bb1, const float* __restrict__ Bb2,
                 float* __restrict__ out, int K)
{
    __shared__ __align__(16) float As[BK][TM];
    __shared__ __align__(16) float Bs[BK][TN];

    const int tid  = threadIdx.x;
    const int row0 = blockIdx.x * TM;
    const int col0 = blockIdx.y * TN;

    float acc[8][8];
    #pragma unroll
    for (int i = 0; i < 8; i++)
        #pragma unroll
        for (int j = 0; j < 8; j++) acc[i][j] = 0.f;

    const int tx = tid & 15;
    const int ty = tid >> 4;

    const int nK = K / BK;
    for (int kt = 0; kt < nK; kt++) {
        const int k0 = kt * BK;
        for (int i = tid; i < TM * (BK / 4); i += 256) {
            int m  = i / (BK / 4);
            int kq = i % (BK / 4);
            float4 v = *reinterpret_cast<const float4*>(
                Asrc + (long)(row0 + m) * K + k0 + kq * 4);
            As[kq * 4 + 0][m] = v.x;
            As[kq * 4 + 1][m] = v.y;
            As[kq * 4 + 2][m] = v.z;
            As[kq * 4 + 3][m] = v.w;
        }
        for (int i = tid; i < BK * (TN / 4); i += 256) {
            int k  = i / (TN / 4);
            int nq = i % (TN / 4);
            int c  = col0 + nq * 4;
            float4 v = make_float4(0.f, 0.f, 0.f, 0.f);
            if (c < NCAT) {
                const float* W = (c < AD) ? W0 : (c < 2 * AD ? W1 : W2);
                int lc = c - (c < AD ? 0 : (c < 2 * AD ? AD : 2 * AD));
                v = *reinterpret_cast<const float4*>(W + (long)(k0 + k) * AD + lc);
            }
            *reinterpret_cast<float4*>(&Bs[k][nq * 4]) = v;
        }
        __syncthreads();
        #pragma unroll
        for (int kk = 0; kk < BK; kk++) {
            float4 a0 = *reinterpret_cast<const float4*>(&As[kk][ty * 4]);
            float4 a1 = *reinterpret_cast<const float4*>(&As[kk][64 + ty * 4]);
            float4 b0 = *reinterpret_cast<const float4*>(&Bs[kk][tx * 4]);
            float4 b1 = *reinterpret_cast<const float4*>(&Bs[kk][64 + tx * 4]);
            float ar[8] = {a0.x, a0.y, a0.z, a0.w, a1.x, a1.y, a1.z, a1.w};
            float br[8] = {b0.x, b0.y, b0.z, b0.w, b1.x, b1.y, b1.z, b1.w};
            #pragma unroll
            for (int i = 0; i < 8; i++)
                #pragma unroll
                for (int j = 0; j < 8; j++)
                    acc[i][j] = fmaf(ar[i], br[j], acc[i][j]);
        }
        __syncthreads();
    }

    #pragma unroll
    for (int jj = 0; jj < 8; jj++) {
        int c = col0 + ((jj < 4) ? (tx * 4 + jj) : (64 + tx * 4 + (jj - 4)));
        if (c >= NCAT) continue;
        const float* Bb = (c < AD) ? Bb0 : (c < 2 * AD ? Bb1 : Bb2);
        float bias = Bb[c - (c < AD ? 0 : (c < 2 * AD ? AD : 2 * AD))];
        #pragma unroll
        for (int ii = 0; ii < 8; ii++) {
            int r = row0 + ((ii < 4) ? (ty * 4 + ii) : (64 + ty * 4 + (ii - 4)));
            float x = acc[ii][jj] + bias;
            out[(long)r * NCAT + c] = (x > 0.f) ? x : expm1f(x);
        }
    }
}

// =====================================================================
// Word-level attention + target attention.  One block per (line, head).
// =====================================================================
__global__ __launch_bounds__(128)
void watt_kernel(const int* __restrict__ docs, const float* __restrict__ w_tgt,
                 float* __restrict__ lineE)
{
    const int line = blockIdx.x;
    const int h    = blockIdx.y;
    const int tid  = threadIdx.x;

    __shared__ float q[WPL * DPH], k[WPL * DPH], v[WPL * DPH];
    __shared__ float ws[WPL * 33];
    __shared__ float watt[WPL * DPH];
    __shared__ float tw[WPL];
    __shared__ int   msk[WPL];

    if (tid < WPL) msk[tid] = (docs[line * WPL + tid] != 0);
    for (int i = tid; i < WPL * DPH; i += 128) {
        int w = i / DPH, d = i % DPH;
        long base = (long)(line * WPL + w) * NCAT + h * DPH + d;
        q[i] = g_wqkv[base];
        k[i] = g_wqkv[base + AD];
        v[i] = g_wqkv[base + 2 * AD];
    }
    __syncthreads();

    {
        int i0 = (tid >> 3) * 2;
        int j0 = (tid & 7) * 4;
        float s0[4] = {0.f, 0.f, 0.f, 0.f};
        float s1[4] = {0.f, 0.f, 0.f, 0.f};
        for (int d = 0; d < DPH; d++) {
            float qa = q[i0 * DPH + d];
            float qb = q[(i0 + 1) * DPH + d];
            #pragma unroll
            for (int jj = 0; jj < 4; jj++) {
                float kv = k[(j0 + jj) * DPH + d];
                s0[jj] = fmaf(qa, kv, s0[jj]);
                s1[jj] = fmaf(qb, kv, s1[jj]);
            }
        }
        #pragma unroll
        for (int jj = 0; jj < 4; jj++) {
            float m = msk[j0 + jj] ? 0.f : NEGPEN;
            ws[i0 * 33 + j0 + jj]       = s0[jj] * INV_SQRT50 - m;
            ws[(i0 + 1) * 33 + j0 + jj] = s1[jj] * INV_SQRT50 - m;
        }
    }
    __syncthreads();

    {
        int wi = tid >> 5, ln = tid & 31;
        for (int r = wi; r < WPL; r += 4) {
            float x = ws[r * 33 + ln];
            float mx = x;
            #pragma unroll
            for (int o = 16; o; o >>= 1) mx = fmaxf(mx, __shfl_xor_sync(~0u, mx, o));
            float e = __expf(x - mx);
            float sm = e;
            #pragma unroll
            for (int o = 16; o; o >>= 1) sm += __shfl_xor_sync(~0u, sm, o);
            float wv = e / sm;
            if (!msk[r]) wv = 0.f;
            ws[r * 33 + ln] = wv;
        }
    }
    __syncthreads();

    for (int u = tid; u < (WPL / 2) * DPH; u += 128) {
        int ip = u / DPH, d = u % DPH;
        int i0 = ip * 2;
        float a0 = 0.f, a1 = 0.f;
        for (int j = 0; j < WPL; j++) {
            float vv = v[j * DPH + d];
            a0 = fmaf(ws[i0 * 33 + j], vv, a0);
            a1 = fmaf(ws[(i0 + 1) * 33 + j], vv, a1);
        }
        watt[i0 * DPH + d] = a0;
        watt[(i0 + 1) * DPH + d] = a1;
    }
    __syncthreads();

    if (tid < WPL) {
        int j = tid;
        float s = 0.f;
        for (int d = 0; d < DPH; d++)
            s = fmaf(w_tgt[h * DPH + d], k[j * DPH + d], s);
        s *= INV_SQRT50;
        if (!msk[j]) s -= NEGPEN;
        float mx = s;
        #pragma unroll
        for (int o = 16; o; o >>= 1) mx = fmaxf(mx, __shfl_xor_sync(~0u, mx, o));
        float e = __expf(s - mx);
        float sm = e;
        #pragma unroll
        for (int o = 16; o; o >>= 1) sm += __shfl_xor_sync(~0u, sm, o);
        tw[j] = e / sm;
    }
    __syncthreads();

    if (tid < DPH) {
        int d = tid;
        float a = 0.f;
        for (int j = 0; j < WPL; j++) a = fmaf(tw[j], watt[j * DPH + d], a);
        lineE[(long)line * AD + h * DPH + d] = a;
    }
}

// =====================================================================
// Line-level attention + doc target attention.  One block per (doc, head).
// =====================================================================
#define LA_Q  0
#define LA_K  (LINES * DPH)
#define LA_V  (2 * LINES * DPH)
#define LA_A  (3 * LINES * DPH)
#define LA_S  (4 * LINES * DPH)
#define LA_FLOATS (LA_S + LINES * 129)
#define LA_SMEM_BYTES (LA_FLOATS * 4)
#define LA_THREADS 512

__global__ __launch_bounds__(LA_THREADS)
void latt_kernel(const int* __restrict__ docs, const float* __restrict__ l_tgt,
                 float* __restrict__ docE)
{
    extern __shared__ float sm[];
    __shared__ int   mskL[LINES];
    __shared__ float ts[LINES];

    const int doc = blockIdx.x;
    const int h   = blockIdx.y;
    const int tid = threadIdx.x;

    if (tid < LINES) {
        int any = 0;
        const int* p = docs + (long)(doc * LINES + tid) * WPL;
        for (int w = 0; w < WPL; w++) any |= p[w];
        mskL[tid] = (any != 0);
    }
    for (int i = tid; i < LINES * DPH; i += LA_THREADS) {
        int l = i / DPH, d = i % DPH;
        long base = (long)(doc * LINES + l) * NCAT + h * DPH + d;
        sm[LA_Q + i] = g_lqkv[base];
        sm[LA_K + i] = g_lqkv[base + AD];
        sm[LA_V + i] = g_lqkv[base + 2 * AD];
    }
    __syncthreads();

    for (int u = tid; u < (LINES / 2) * (LINES / 4); u += LA_THREADS) {
        int ip = u >> 5;
        int jq = u & 31;
        int i0 = ip * 2, j0 = jq * 4;
        float s0[4] = {0.f, 0.f, 0.f, 0.f};
        float s1[4] = {0.f, 0.f, 0.f, 0.f};
        for (int d = 0; d < DPH; d++) {
            float qa = sm[LA_Q + i0 * DPH + d];
            float qb = sm[LA_Q + (i0 + 1) * DPH + d];
            #pragma unroll
            for (int jj = 0; jj < 4; jj++) {
                float kv = sm[LA_K + (j0 + jj) * DPH + d];
                s0[jj] = fmaf(qa, kv, s0[jj]);
                s1[jj] = fmaf(qb, kv, s1[jj]);
            }
        }
        #pragma unroll
        for (int jj = 0; jj < 4; jj++) {
            float m = mskL[j0 + jj] ? 0.f : NEGPEN;
            sm[LA_S + i0 * 129 + j0 + jj]       = s0[jj] * INV_SQRT50 - m;
            sm[LA_S + (i0 + 1) * 129 + j0 + jj] = s1[jj] * INV_SQRT50 - m;
        }
    }
    __syncthreads();

    {
        int wi = tid >> 5, ln = tid & 31;
        for (int r = wi; r < LINES; r += (LA_THREADS / 32)) {
            float x0 = sm[LA_S + r * 129 + ln];
            float x1 = sm[LA_S + r * 129 + ln + 32];
            float x2 = sm[LA_S + r * 129 + ln + 64];
            float x3 = sm[LA_S + r * 129 + ln + 96];
            float mx = fmaxf(fmaxf(x0, x1), fmaxf(x2, x3));
            #pragma unroll
            for (int o = 16; o; o >>= 1) mx = fmaxf(mx, __shfl_xor_sync(~0u, mx, o));
            float e0 = __expf(x0 - mx), e1 = __expf(x1 - mx);
            float e2 = __expf(x2 - mx), e3 = __expf(x3 - mx);
            float smv = e0 + e1 + e2 + e3;
            #pragma unroll
            for (int o = 16; o; o >>= 1) smv += __shfl_xor_sync(~0u, smv, o);
            float inv = (mskL[r] ? 1.f : 0.f) / smv;
            sm[LA_S + r * 129 + ln]      = e0 * inv;
            sm[LA_S + r * 129 + ln + 32] = e1 * inv;
            sm[LA_S + r * 129 + ln + 64] = e2 * inv;
            sm[LA_S + r * 129 + ln + 96] = e3 * inv;
        }
    }
    __syncthreads();

    for (int u = tid; u < (LINES / 2) * DPH; u += LA_THREADS) {
        int ip = u / DPH, d = u % DPH;
        int i0 = ip * 2;
        float a0 = 0.f, a1 = 0.f;
        for (int j = 0; j < LINES; j++) {
            float vv = sm[LA_V + j * DPH + d];
            a0 = fmaf(sm[LA_S + i0 * 129 + j], vv, a0);
            a1 = fmaf(sm[LA_S + (i0 + 1) * 129 + j], vv, a1);
        }
        sm[LA_A + i0 * DPH + d] = a0;
        sm[LA_A + (i0 + 1) * DPH + d] = a1;
    }
    __syncthreads();

    if (tid < LINES) {
        int j = tid;
        float s = 0.f;
        for (int d = 0; d < DPH; d++)
            s = fmaf(l_tgt[h * DPH + d], sm[LA_K + j * DPH + d], s);
        s *= INV_SQRT50;
        if (!mskL[j]) s -= NEGPEN;
        ts[j] = s;
    }
    __syncthreads();
    if (tid < 32) {
        int ln = tid;
        float x0 = ts[ln], x1 = ts[ln + 32], x2 = ts[ln + 64], x3 = ts[ln + 96];
        float mx = fmaxf(fmaxf(x0, x1), fmaxf(x2, x3));
        #pragma unroll
        for (int o = 16; o; o >>= 1) mx = fmaxf(mx, __shfl_xor_sync(~0u, mx, o));
        float e0 = __expf(x0 - mx), e1 = __expf(x1 - mx);
        float e2 = __expf(x2 - mx), e3 = __expf(x3 - mx);
        float smv = e0 + e1 + e2 + e3;
        #pragma unroll
        for (int o = 16; o; o >>= 1) smv += __shfl_xor_sync(~0u, smv, o);
        float inv = 1.f / smv;
        ts[ln] = e0 * inv; ts[ln + 32] = e1 * inv;
        ts[ln + 64] = e2 * inv; ts[ln + 96] = e3 * inv;
    }
    __syncthreads();
    if (tid < DPH) {
        int d = tid;
        float a = 0.f;
        for (int j = 0; j < LINES; j++) a = fmaf(ts[j], sm[LA_A + j * DPH + d], a);
        docE[(long)doc * AD + h * DPH + d] = a;
    }
}

// =====================================================================
// Final FC
// =====================================================================
__global__ __launch_bounds__(608)
void fc_kernel(const float* __restrict__ fc1w, const float* __restrict__ fc1b,
               const float* __restrict__ fc2w, const float* __restrict__ fc2b,
               float* __restrict__ out)
{
    const int b = blockIdx.x;
    const int tid = threadIdx.x;
    __shared__ float de[AD];
    for (int i = tid; i < AD; i += 608) de[i] = g_docE[b * AD + i];
    __syncthreads();
    if (tid < 582) {
        float a;
        if (tid < 70) {
            a = fc1b[tid];
            for (int kk = 0; kk < AD; kk++) a = fmaf(de[kk], fc1w[kk * 70 + tid], a);
        } else {
            int c = tid - 70;
            a = fc2b[c];
            for (int kk = 0; kk < AD; kk++) a = fmaf(de[kk], fc2w[kk * 512 + c], a);
        }
        out[b * 582 + tid] = a;
    }
}

// =====================================================================
extern "C" void kernel_launch(void* const* d_in, const int* in_sizes, int n_in,
                              void* d_out, int out_size)
{
    const int*   docs  = (const int*)  d_in[0];
    const float* emb   = (const float*)d_in[1];
    const float* wq_w  = (const float*)d_in[2];
    const float* wq_b  = (const float*)d_in[3];
    const float* wk_w  = (const float*)d_in[4];
    const float* wk_b  = (const float*)d_in[5];
    const float* wv_w  = (const float*)d_in[6];
    const float* wv_b  = (const float*)d_in[7];
    const float* w_tgt = (const float*)d_in[8];
    const float* lq_w  = (const float*)d_in[9];
    const float* lq_b  = (const float*)d_in[10];
    const float* lk_w  = (const float*)d_in[11];
    const float* lk_b  = (const float*)d_in[12];
    const float* lv_w  = (const float*)d_in[13];
    const float* lv_b  = (const float*)d_in[14];
    const float* l_tgt = (const float*)d_in[15];
    const float* fc1_w = (const float*)d_in[16];
    const float* fc1_b = (const float*)d_in[17];
    const float* fc2_w = (const float*)d_in[18];
    const float* fc2_b = (const float*)d_in[19];
    float* out = (float*)d_out;

    float *wqkv, *lineE, *lqkv, *docE;
    cudaGetSymbolAddress((void**)&wqkv,  g_wqkv);
    cudaGetSymbolAddress((void**)&lineE, g_lineE);
    cudaGetSymbolAddress((void**)&lqkv,  g_lqkv);
    cudaGetSymbolAddress((void**)&docE,  g_docE);

    // 0) split word-proj weights into fp16 hi/lo, K-major
    splitB_kernel<<<(NCAT * (KPAD / 2) + 255) / 256, 256>>>(wq_w, wk_w, wv_w);

    // 1) word projections via mma.sync fp16 hi/lo (fp32-class accuracy)
    cudaFuncSetAttribute(proj_mma_kernel, cudaFuncAttributeMaxDynamicSharedMemorySize,
                         PROJ_SMEM);
    proj_mma_kernel<<<NTOK / 128, 256, PROJ_SMEM>>>(
        docs, emb, wq_b, wk_b, wv_b, wqkv);

    // 2) word attention + target attention -> line_e [2048,400]
    watt_kernel<<<dim3(NLINE, HEADS), 128>>>(docs, w_tgt, lineE);

    // 3) line projections (small): [2048,400]x[400,1200]
    proj_kernel<<<dim3(NLINE / TM, 10), 256>>>(
        lineE, lq_w, lk_w, lv_w, lq_b, lk_b, lv_b, lqkv, AD);

    // 4) line attention + doc target attention -> doc_e [16,400]
    cudaFuncSetAttribute(latt_kernel, cudaFuncAttributeMaxDynamicSharedMemorySize,
                         LA_SMEM_BYTES);
    latt_kernel<<<dim3(B_SZ, HEADS), LA_THREADS, LA_SMEM_BYTES>>>(docs, l_tgt, docE);

    // 5) final FC -> [16,582]
    fc_kernel<<<B_SZ, 608>>>(fc1_w, fc1_b, fc2_w, fc2_b, out);
}

// round 4
// speedup vs baseline: 2.3251x; 1.6381x over previous
#include <cuda_runtime.h>
#include <cuda_fp16.h>
#include <cstdint>

// ---------------- constants ----------------
#define B_SZ   16
#define LINES  128
#define WPL    32
#define NLINE  (B_SZ*LINES)          // 2048
#define NTOK   (NLINE*WPL)           // 65536
#define EMB_D  300
#define AD     400
#define HEADS  8
#define DPH    50
#define NCAT   1200                  // q|k|v concatenated
#define VOCAB  30000
#define VTILES 235                   // ceil(30000/128)
#define INV_SQRT50 0.14142135623730951f
#define NEGPEN 1e7f

// GEMM tiling
#define KPAD    320
#define APITCH  328              // half elements per A row (656B -> conflict-free)
#define NT      80               // N tile
#define KC      64               // K chunk
#define NCHUNK  5                // 320/64
#define BPITCH  72               // half elements per B row (144B)
#define BBUF    (NT*BPITCH)      // 5760 halves per (buf,split)

// ---------------- scratch (device globals; no allocation allowed) ----------------
__device__ float g_vproj[(long)VOCAB * NCAT]; // [30000][1200] per-vocab q|k|v proj
__device__ float g_lineE[NLINE * AD];          // [2048][400]
__device__ float g_lqkv[NLINE * NCAT];         // [2048][1200]
__device__ float g_docE[B_SZ * AD];            // [16][400]
__device__ __align__(16) __half g_Bhi[NCAT * KPAD];  // [1200][320] K-major
__device__ __align__(16) __half g_Blo[NCAT * KPAD];

// ---------------- small PTX helpers (baseline ISA only) ----------------
__device__ __forceinline__ void cp16(void* dst, const void* src) {
    uint32_t d = (uint32_t)__cvta_generic_to_shared(dst);
    asm volatile("cp.async.ca.shared.global [%0], [%1], 16;" :: "r"(d), "l"(src));
}
__device__ __forceinline__ void cp_commit() {
    asm volatile("cp.async.commit_group;" ::: "memory");
}
template<int N>
__device__ __forceinline__ void cp_wait() {
    asm volatile("cp.async.wait_group %0;" :: "n"(N) : "memory");
}
__device__ __forceinline__ void mma16816(float* c, const uint32_t* a, const uint32_t* b) {
    asm volatile("mma.sync.aligned.m16n8k16.row.col.f32.f16.f16.f32 "
        "{%0,%1,%2,%3}, {%4,%5,%6,%7}, {%8,%9}, {%0,%1,%2,%3};"
        : "+f"(c[0]), "+f"(c[1]), "+f"(c[2]), "+f"(c[3])
        : "r"(a[0]), "r"(a[1]), "r"(a[2]), "r"(a[3]), "r"(b[0]), "r"(b[1]));
}
__device__ __forceinline__ uint32_t ld32s(const __half* p) {
    return *reinterpret_cast<const uint32_t*>(p);
}

// =====================================================================
// Prep: split W [300][400]x3 -> g_Bhi/g_Blo [1200 n][320 k] fp16 (K zero-padded)
// =====================================================================
__global__ __launch_bounds__(256)
void splitB_kernel(const float* __restrict__ W0, const float* __restrict__ W1,
                   const float* __restrict__ W2)
{
    int idx = blockIdx.x * 256 + threadIdx.x;    // over 1200*160
    if (idx >= NCAT * (KPAD / 2)) return;
    int n  = idx / (KPAD / 2);
    int k0 = (idx % (KPAD / 2)) * 2;
    const float* W = (n < AD) ? W0 : (n < 2 * AD ? W1 : W2);
    int lc = (n < AD) ? n : (n < 2 * AD ? n - AD : n - 2 * AD);
    float x0 = (k0     < EMB_D) ? W[k0 * AD + lc]       : 0.f;
    float x1 = (k0 + 1 < EMB_D) ? W[(k0 + 1) * AD + lc] : 0.f;
    __half h0 = __float2half(x0), h1 = __float2half(x1);
    __half l0 = __float2half(x0 - __half2float(h0));
    __half l1 = __float2half(x1 - __half2float(h1));
    *reinterpret_cast<__half2*>(g_Bhi + n * KPAD + k0) = __halves2half2(h0, h1);
    *reinterpret_cast<__half2*>(g_Blo + n * KPAD + k0) = __halves2half2(l0, l1);
}

// =====================================================================
// Vocab projection GEMM (mma.sync fp16 hi/lo 3-term):
//   g_vproj[30000][1200] = elu(emb @ [Wq|Wk|Wv] + bias)
// grid (235 M-tiles, 3 N-splits of 5 tiles), 512 threads (16 warps: 8M x 2N).
// =====================================================================
#define PROJ_SMEM ((2 * 128 * APITCH + 2 * 2 * BBUF) * 2)   // 214016 B

__global__ __launch_bounds__(512, 1)
void proj_vocab_kernel(const float* __restrict__ emb,
                       const float* __restrict__ Bb0, const float* __restrict__ Bb1,
                       const float* __restrict__ Bb2,
                       float* __restrict__ out)
{
    extern __shared__ __half sh[];
    __half* sAhi = sh;
    __half* sAlo = sAhi + 128 * APITCH;
    __half* sB   = sAlo + 128 * APITCH;     // [2 buf][2 split][NT*BPITCH]

    const int tid  = threadIdx.x;
    const int wid  = tid >> 5;
    const int lane = tid & 31;
    const int g4 = lane >> 2;               // 0..7
    const int l4 = lane & 3;                // 0..3
    const int wm = wid >> 1;                // 0..7 (M slab of 16)
    const int wn = wid & 1;                 // 0..1 (N slab of 40)
    const int bx = blockIdx.x;
    const int by = blockIdx.y;              // 0..2 : 5 N-tiles each

    // ---- load + hi/lo split A (128 vocab rows, clamped at tail) ----
    for (int idx = tid; idx < 128 * (KPAD / 2); idx += 512) {
        int m  = idx / (KPAD / 2);
        int k0 = (idx % (KPAD / 2)) * 2;
        int r = bx * 128 + m;
        if (r >= VOCAB) r = VOCAB - 1;
        float x0 = 0.f, x1 = 0.f;
        if (k0 < EMB_D) {
            float2 v = *reinterpret_cast<const float2*>(emb + (long)r * EMB_D + k0);
            x0 = v.x; x1 = v.y;
        }
        __half h0 = __float2half(x0), h1 = __float2half(x1);
        __half l0 = __float2half(x0 - __half2float(h0));
        __half l1 = __float2half(x1 - __half2float(h1));
        *reinterpret_cast<__half2*>(sAhi + m * APITCH + k0) = __halves2half2(h0, h1);
        *reinterpret_cast<__half2*>(sAlo + m * APITCH + k0) = __halves2half2(l0, l1);
    }

    auto prefetchB = [&](int lc) {
        int nt2 = by * 5 + lc / NCHUNK;
        int kc2 = lc % NCHUNK;
        int buf = lc & 1;
        int colbase = nt2 * NT;
        for (int idx = tid; idx < 1280; idx += 512) {
            int split = idx / 640;
            int rem   = idx % 640;
            int n   = rem >> 3;
            int seg = rem & 7;
            const __half* src = (split ? g_Blo : g_Bhi)
                              + (long)(colbase + n) * KPAD + kc2 * KC + seg * 8;
            __half* dst = sB + (buf * 2 + split) * BBUF + n * BPITCH + seg * 8;
            cp16(dst, src);
        }
    };

    prefetchB(0);
    cp_commit();
    __syncthreads();   // A tile ready

    const __half* pAh = sAhi + (wm * 16 + g4) * APITCH;
    const __half* pAl = sAlo + (wm * 16 + g4) * APITCH;

    for (int lt = 0; lt < 5; lt++) {
        const int nt = by * 5 + lt;
        float acc[5][4];
        #pragma unroll
        for (int ni = 0; ni < 5; ni++)
            #pragma unroll
            for (int r = 0; r < 4; r++) acc[ni][r] = 0.f;

        for (int kc = 0; kc < NCHUNK; kc++) {
            const int lc = lt * NCHUNK + kc;
            if (lc + 1 < 25) { prefetchB(lc + 1); cp_commit(); cp_wait<1>(); }
            else             { cp_wait<0>(); }
            __syncthreads();

            const int buf = lc & 1;
            const __half* pBh = sB + (buf * 2 + 0) * BBUF + (wn * 40 + g4) * BPITCH;
            const __half* pBl = sB + (buf * 2 + 1) * BBUF + (wn * 40 + g4) * BPITCH;

            #pragma unroll
            for (int ks = 0; ks < 4; ks++) {
                const int kA = kc * KC + ks * 16 + l4 * 2;
                uint32_t ah[4], al[4];
                ah[0] = ld32s(pAh + kA);
                ah[1] = ld32s(pAh + 8 * APITCH + kA);
                ah[2] = ld32s(pAh + kA + 8);
                ah[3] = ld32s(pAh + 8 * APITCH + kA + 8);
                al[0] = ld32s(pAl + kA);
                al[1] = ld32s(pAl + 8 * APITCH + kA);
                al[2] = ld32s(pAl + kA + 8);
                al[3] = ld32s(pAl + 8 * APITCH + kA + 8);

                uint32_t bh[5][2], bl[5][2];
                const int kk = ks * 16 + l4 * 2;
                #pragma unroll
                for (int ni = 0; ni < 5; ni++) {
                    bh[ni][0] = ld32s(pBh + ni * (8 * BPITCH) + kk);
                    bh[ni][1] = ld32s(pBh + ni * (8 * BPITCH) + kk + 8);
                    bl[ni][0] = ld32s(pBl + ni * (8 * BPITCH) + kk);
                    bl[ni][1] = ld32s(pBl + ni * (8 * BPITCH) + kk + 8);
                }
                #pragma unroll
                for (int ni = 0; ni < 5; ni++) {
                    mma16816(acc[ni], ah, bh[ni]);
                    mma16816(acc[ni], ah, bl[ni]);
                    mma16816(acc[ni], al, bh[ni]);
                }
            }
            __syncthreads();
        }

        // ---- epilogue: bias + ELU + guarded store ----
        const float* Bb = (by == 0) ? Bb0 : (by == 1 ? Bb1 : Bb2);
        const int cb = nt * NT - by * AD;
        #pragma unroll
        for (int r01 = 0; r01 < 2; r01++) {
            const int row = bx * 128 + wm * 16 + g4 + r01 * 8;
            if (row < VOCAB) {
                #pragma unroll
                for (int ni = 0; ni < 5; ni++) {
                    int lc2 = cb + wn * 40 + ni * 8 + l4 * 2;
                    float x0 = acc[ni][r01 * 2 + 0] + Bb[lc2];
                    float x1 = acc[ni][r01 * 2 + 1] + Bb[lc2 + 1];
                    float2 o;
                    o.x = (x0 > 0.f) ? x0 : expm1f(x0);
                    o.y = (x1 > 0.f) ? x1 : expm1f(x1);
                    int col = nt * NT + wn * 40 + ni * 8 + l4 * 2;
                    *reinterpret_cast<float2*>(out + (long)row * NCAT + col) = o;
                }
            }
        }
    }
}

// =====================================================================
// Line projection FFMA GEMM, 64x80 tiles (480 CTAs), thread tile 4x5.
//   g_lqkv[2048][1200] = elu(lineE @ [Wq|Wk|Wv] + bias)
// =====================================================================
#define P2_BK 16

__global__ __launch_bounds__(256)
void proj2_kernel(const float* __restrict__ Asrc,
                  const float* __restrict__ W0, const float* __restrict__ W1,
                  const float* __restrict__ W2,
                  const float* __restrict__ Bb0, const float* __restrict__ Bb1,
                  const float* __restrict__ Bb2,
                  float* __restrict__ out)
{
    __shared__ __align__(16) float As[P2_BK][64];
    __shared__ __align__(16) float Bs[P2_BK][80];

    const int tid  = threadIdx.x;
    const int tx = tid & 15;            // 5 cols each (stride 16)
    const int ty = tid >> 4;            // 4 rows each
    const int row0 = blockIdx.x * 64;
    const int col0 = blockIdx.y * 80;   // within one weight matrix (80 | 400)
    const int sel = blockIdx.y / 5;     // 0,1,2
    const float* W  = (sel == 0) ? W0 : (sel == 1 ? W1 : W2);
    const float* Bb = (sel == 0) ? Bb0 : (sel == 1 ? Bb1 : Bb2);
    const int lcb = col0 - sel * AD;

    float acc[4][5];
    #pragma unroll
    for (int i = 0; i < 4; i++)
        #pragma unroll
        for (int j = 0; j < 5; j++) acc[i][j] = 0.f;

    for (int kt = 0; kt < AD / P2_BK; kt++) {
        const int k0 = kt * P2_BK;
        {   // As[k][m] transposed, float4 along k
            int m  = tid >> 2;
            int kq = tid & 3;
            float4 v = *reinterpret_cast<const float4*>(
                Asrc + (long)(row0 + m) * AD + k0 + kq * 4);
            As[kq * 4 + 0][m] = v.x;
            As[kq * 4 + 1][m] = v.y;
            As[kq * 4 + 2][m] = v.z;
            As[kq * 4 + 3][m] = v.w;
        }
        for (int idx = tid; idx < P2_BK * 20; idx += 256) {
            int k  = idx / 20;
            int nq = idx % 20;
            float4 v = *reinterpret_cast<const float4*>(
                W + (long)(k0 + k) * AD + lcb + nq * 4);
            *reinterpret_cast<float4*>(&Bs[k][nq * 4]) = v;
        }
        __syncthreads();
        #pragma unroll
        for (int kk = 0; kk < P2_BK; kk++) {
            float4 a = *reinterpret_cast<const float4*>(&As[kk][ty * 4]);
            float ar[4] = {a.x, a.y, a.z, a.w};
            float br[5];
            #pragma unroll
            for (int j = 0; j < 5; j++) br[j] = Bs[kk][j * 16 + tx];
            #pragma unroll
            for (int i = 0; i < 4; i++)
                #pragma unroll
                for (int j = 0; j < 5; j++)
                    acc[i][j] = fmaf(ar[i], br[j], acc[i][j]);
        }
        __syncthreads();
    }

    #pragma unroll
    for (int j = 0; j < 5; j++) {
        int lc = lcb + j * 16 + tx;
        float bias = Bb[lc];
        int col = col0 + j * 16 + tx;
        #pragma unroll
        for (int i = 0; i < 4; i++) {
            int r = row0 + ty * 4 + i;
            float x = acc[i][j] + bias;
            out[(long)r * NCAT + col] = (x > 0.f) ? x : expm1f(x);
        }
    }
}

// =====================================================================
// Word-level attention + target attention.  One block per (line, head).
// Reads q/k/v from the precomputed vocab table.
// =====================================================================
__global__ __launch_bounds__(128)
void watt_kernel(const int* __restrict__ docs, const float* __restrict__ w_tgt,
                 float* __restrict__ lineE)
{
    const int line = blockIdx.x;
    const int h    = blockIdx.y;
    const int tid  = threadIdx.x;

    __shared__ float q[WPL * DPH], k[WPL * DPH], v[WPL * DPH];
    __shared__ float ws[WPL * 33];
    __shared__ float watt[WPL * DPH];
    __shared__ float tw[WPL];
    __shared__ int   msk[WPL];
    __shared__ int   stok[WPL];

    if (tid < WPL) {
        int t = docs[line * WPL + tid];
        stok[tid] = t;
        msk[tid] = (t != 0);
    }
    __syncthreads();
    for (int i = tid; i < WPL * DPH; i += 128) {
        int w = i / DPH, d = i % DPH;
        long base = (long)stok[w] * NCAT + h * DPH + d;
        q[i] = g_vproj[base];
        k[i] = g_vproj[base + AD];
        v[i] = g_vproj[base + 2 * AD];
    }
    __syncthreads();

    {
        int i0 = (tid >> 3) * 2;
        int j0 = (tid & 7) * 4;
        float s0[4] = {0.f, 0.f, 0.f, 0.f};
        float s1[4] = {0.f, 0.f, 0.f, 0.f};
        for (int d = 0; d < DPH; d++) {
            float qa = q[i0 * DPH + d];
            float qb = q[(i0 + 1) * DPH + d];
            #pragma unroll
            for (int jj = 0; jj < 4; jj++) {
                float kv = k[(j0 + jj) * DPH + d];
                s0[jj] = fmaf(qa, kv, s0[jj]);
                s1[jj] = fmaf(qb, kv, s1[jj]);
            }
        }
        #pragma unroll
        for (int jj = 0; jj < 4; jj++) {
            float m = msk[j0 + jj] ? 0.f : NEGPEN;
            ws[i0 * 33 + j0 + jj]       = s0[jj] * INV_SQRT50 - m;
            ws[(i0 + 1) * 33 + j0 + jj] = s1[jj] * INV_SQRT50 - m;
        }
    }
    __syncthreads();

    {
        int wi = tid >> 5, ln = tid & 31;
        for (int r = wi; r < WPL; r += 4) {
            float x = ws[r * 33 + ln];
            float mx = x;
            #pragma unroll
            for (int o = 16; o; o >>= 1) mx = fmaxf(mx, __shfl_xor_sync(~0u, mx, o));
            float e = __expf(x - mx);
            float sm = e;
            #pragma unroll
            for (int o = 16; o; o >>= 1) sm += __shfl_xor_sync(~0u, sm, o);
            float wv = e / sm;
            if (!msk[r]) wv = 0.f;
            ws[r * 33 + ln] = wv;
        }
    }
    __syncthreads();

    for (int u = tid; u < (WPL / 2) * DPH; u += 128) {
        int ip = u / DPH, d = u % DPH;
        int i0 = ip * 2;
        float a0 = 0.f, a1 = 0.f;
        for (int j = 0; j < WPL; j++) {
            float vv = v[j * DPH + d];
            a0 = fmaf(ws[i0 * 33 + j], vv, a0);
            a1 = fmaf(ws[(i0 + 1) * 33 + j], vv, a1);
        }
        watt[i0 * DPH + d] = a0;
        watt[(i0 + 1) * DPH + d] = a1;
    }
    __syncthreads();

    if (tid < WPL) {
        int j = tid;
        float s = 0.f;
        for (int d = 0; d < DPH; d++)
            s = fmaf(w_tgt[h * DPH + d], k[j * DPH + d], s);
        s *= INV_SQRT50;
        if (!msk[j]) s -= NEGPEN;
        float mx = s;
        #pragma unroll
        for (int o = 16; o; o >>= 1) mx = fmaxf(mx, __shfl_xor_sync(~0u, mx, o));
        float e = __expf(s - mx);
        float sm = e;
        #pragma unroll
        for (int o = 16; o; o >>= 1) sm += __shfl_xor_sync(~0u, sm, o);
        tw[j] = e / sm;
    }
    __syncthreads();

    if (tid < DPH) {
        int d = tid;
        float a = 0.f;
        for (int j = 0; j < WPL; j++) a = fmaf(tw[j], watt[j * DPH + d], a);
        lineE[(long)line * AD + h * DPH + d] = a;
    }
}

// =====================================================================
// Line-level attention + doc target attention.  One block per (doc, head).
// =====================================================================
#define LA_Q  0
#define LA_K  (LINES * DPH)
#define LA_V  (2 * LINES * DPH)
#define LA_A  (3 * LINES * DPH)
#define LA_S  (4 * LINES * DPH)
#define LA_FLOATS (LA_S + LINES * 129)
#define LA_SMEM_BYTES (LA_FLOATS * 4)
#define LA_THREADS 512

__global__ __launch_bounds__(LA_THREADS)
void latt_kernel(const int* __restrict__ docs, const float* __restrict__ l_tgt,
                 float* __restrict__ docE)
{
    extern __shared__ float sm[];
    __shared__ int   mskL[LINES];
    __shared__ float ts[LINES];

    const int doc = blockIdx.x;
    const int h   = blockIdx.y;
    const int tid = threadIdx.x;

    if (tid < LINES) {
        int any = 0;
        const int* p = docs + (long)(doc * LINES + tid) * WPL;
        for (int w = 0; w < WPL; w++) any |= p[w];
        mskL[tid] = (any != 0);
    }
    for (int i = tid; i < LINES * DPH; i += LA_THREADS) {
        int l = i / DPH, d = i % DPH;
        long base = (long)(doc * LINES + l) * NCAT + h * DPH + d;
        sm[LA_Q + i] = g_lqkv[base];
        sm[LA_K + i] = g_lqkv[base + AD];
        sm[LA_V + i] = g_lqkv[base + 2 * AD];
    }
    __syncthreads();

    for (int u = tid; u < (LINES / 2) * (LINES / 4); u += LA_THREADS) {
        int ip = u >> 5;
        int jq = u & 31;
        int i0 = ip * 2, j0 = jq * 4;
        float s0[4] = {0.f, 0.f, 0.f, 0.f};
        float s1[4] = {0.f, 0.f, 0.f, 0.f};
        for (int d = 0; d < DPH; d++) {
            float qa = sm[LA_Q + i0 * DPH + d];
            float qb = sm[LA_Q + (i0 + 1) * DPH + d];
            #pragma unroll
            for (int jj = 0; jj < 4; jj++) {
                float kv = sm[LA_K + (j0 + jj) * DPH + d];
                s0[jj] = fmaf(qa, kv, s0[jj]);
                s1[jj] = fmaf(qb, kv, s1[jj]);
            }
        }
        #pragma unroll
        for (int jj = 0; jj < 4; jj++) {
            float m = mskL[j0 + jj] ? 0.f : NEGPEN;
            sm[LA_S + i0 * 129 + j0 + jj]       = s0[jj] * INV_SQRT50 - m;
            sm[LA_S + (i0 + 1) * 129 + j0 + jj] = s1[jj] * INV_SQRT50 - m;
        }
    }
    __syncthreads();

    {
        int wi = tid >> 5, ln = tid & 31;
        for (int r = wi; r < LINES; r += (LA_THREADS / 32)) {
            float x0 = sm[LA_S + r * 129 + ln];
            float x1 = sm[LA_S + r * 129 + ln + 32];
            float x2 = sm[LA_S + r * 129 + ln + 64];
            float x3 = sm[LA_S + r * 129 + ln + 96];
            float mx = fmaxf(fmaxf(x0, x1), fmaxf(x2, x3));
            #pragma unroll
            for (int o = 16; o; o >>= 1) mx = fmaxf(mx, __shfl_xor_sync(~0u, mx, o));
            float e0 = __expf(x0 - mx), e1 = __expf(x1 - mx);
            float e2 = __expf(x2 - mx), e3 = __expf(x3 - mx);
            float smv = e0 + e1 + e2 + e3;
            #pragma unroll
            for (int o = 16; o; o >>= 1) smv += __shfl_xor_sync(~0u, smv, o);
            float inv = (mskL[r] ? 1.f : 0.f) / smv;
            sm[LA_S + r * 129 + ln]      = e0 * inv;
            sm[LA_S + r * 129 + ln + 32] = e1 * inv;
            sm[LA_S + r * 129 + ln + 64] = e2 * inv;
            sm[LA_S + r * 129 + ln + 96] = e3 * inv;
        }
    }
    __syncthreads();

    for (int u = tid; u < (LINES / 2) * DPH; u += LA_THREADS) {
        int ip = u / DPH, d = u % DPH;
        int i0 = ip * 2;
        float a0 = 0.f, a1 = 0.f;
        for (int j = 0; j < LINES; j++) {
            float vv = sm[LA_V + j * DPH + d];
            a0 = fmaf(sm[LA_S + i0 * 129 + j], vv, a0);
            a1 = fmaf(sm[LA_S + (i0 + 1) * 129 + j], vv, a1);
        }
        sm[LA_A + i0 * DPH + d] = a0;
        sm[LA_A + (i0 + 1) * DPH + d] = a1;
    }
    __syncthreads();

    if (tid < LINES) {
        int j = tid;
        float s = 0.f;
        for (int d = 0; d < DPH; d++)
            s = fmaf(l_tgt[h * DPH + d], sm[LA_K + j * DPH + d], s);
        s *= INV_SQRT50;
        if (!mskL[j]) s -= NEGPEN;
        ts[j] = s;
    }
    __syncthreads();
    if (tid < 32) {
        int ln = tid;
        float x0 = ts[ln], x1 = ts[ln + 32], x2 = ts[ln + 64], x3 = ts[ln + 96];
        float mx = fmaxf(fmaxf(x0, x1), fmaxf(x2, x3));
        #pragma unroll
        for (int o = 16; o; o >>= 1) mx = fmaxf(mx, __shfl_xor_sync(~0u, mx, o));
        float e0 = __expf(x0 - mx), e1 = __expf(x1 - mx);
        float e2 = __expf(x2 - mx), e3 = __expf(x3 - mx);
        float smv = e0 + e1 + e2 + e3;
        #pragma unroll
        for (int o = 16; o; o >>= 1) smv += __shfl_xor_sync(~0u, smv, o);
        float inv = 1.f / smv;
        ts[ln] = e0 * inv; ts[ln + 32] = e1 * inv;
        ts[ln + 64] = e2 * inv; ts[ln + 96] = e3 * inv;
    }
    __syncthreads();
    if (tid < DPH) {
        int d = tid;
        float a = 0.f;
        for (int j = 0; j < LINES; j++) a = fmaf(ts[j], sm[LA_A + j * DPH + d], a);
        docE[(long)doc * AD + h * DPH + d] = a;
    }
}

// =====================================================================
// Final FC
// =====================================================================
__global__ __launch_bounds__(608)
void fc_kernel(const float* __restrict__ fc1w, const float* __restrict__ fc1b,
               const float* __restrict__ fc2w, const float* __restrict__ fc2b,
               float* __restrict__ out)
{
    const int b = blockIdx.x;
    const int tid = threadIdx.x;
    __shared__ float de[AD];
    for (int i = tid; i < AD; i += 608) de[i] = g_docE[b * AD + i];
    __syncthreads();
    if (tid < 582) {
        float a;
        if (tid < 70) {
            a = fc1b[tid];
            for (int kk = 0; kk < AD; kk++) a = fmaf(de[kk], fc1w[kk * 70 + tid], a);
        } else {
            int c = tid - 70;
            a = fc2b[c];
            for (int kk = 0; kk < AD; kk++) a = fmaf(de[kk], fc2w[kk * 512 + c], a);
        }
        out[b * 582 + tid] = a;
    }
}

// =====================================================================
extern "C" void kernel_launch(void* const* d_in, const int* in_sizes, int n_in,
                              void* d_out, int out_size)
{
    const int*   docs  = (const int*)  d_in[0];
    const float* emb   = (const float*)d_in[1];
    const float* wq_w  = (const float*)d_in[2];
    const float* wq_b  = (const float*)d_in[3];
    const float* wk_w  = (const float*)d_in[4];
    const float* wk_b  = (const float*)d_in[5];
    const float* wv_w  = (const float*)d_in[6];
    const float* wv_b  = (const float*)d_in[7];
    const float* w_tgt = (const float*)d_in[8];
    const float* lq_w  = (const float*)d_in[9];
    const float* lq_b  = (const float*)d_in[10];
    const float* lk_w  = (const float*)d_in[11];
    const float* lk_b  = (const float*)d_in[12];
    const float* lv_w  = (const float*)d_in[13];
    const float* lv_b  = (const float*)d_in[14];
    const float* l_tgt = (const float*)d_in[15];
    const float* fc1_w = (const float*)d_in[16];
    const float* fc1_b = (const float*)d_in[17];
    const float* fc2_w = (const float*)d_in[18];
    const float* fc2_b = (const float*)d_in[19];
    float* out = (float*)d_out;

    float *vproj, *lineE, *lqkv, *docE;
    cudaGetSymbolAddress((void**)&vproj, g_vproj);
    cudaGetSymbolAddress((void**)&lineE, g_lineE);
    cudaGetSymbolAddress((void**)&lqkv,  g_lqkv);
    cudaGetSymbolAddress((void**)&docE,  g_docE);

    // 0) split word-proj weights into fp16 hi/lo, K-major
    splitB_kernel<<<(NCAT * (KPAD / 2) + 255) / 256, 256>>>(wq_w, wk_w, wv_w);

    // 1) vocab-wide projection (2.2x less work than per-token)
    cudaFuncSetAttribute(proj_vocab_kernel, cudaFuncAttributeMaxDynamicSharedMemorySize,
                         PROJ_SMEM);
    proj_vocab_kernel<<<dim3(VTILES, 3), 512, PROJ_SMEM>>>(
        emb, wq_b, wk_b, wv_b, vproj);

    // 2) word attention + target attention -> line_e [2048,400]
    watt_kernel<<<dim3(NLINE, HEADS), 128>>>(docs, w_tgt, lineE);

    // 3) line projections: [2048,400]x[400,1200]
    proj2_kernel<<<dim3(NLINE / 64, 15), 256>>>(
        lineE, lq_w, lk_w, lv_w, lq_b, lk_b, lv_b, lqkv);

    // 4) line attention + doc target attention -> doc_e [16,400]
    cudaFuncSetAttribute(latt_kernel, cudaFuncAttributeMaxDynamicSharedMemorySize,
                         LA_SMEM_BYTES);
    latt_kernel<<<dim3(B_SZ, HEADS), LA_THREADS, LA_SMEM_BYTES>>>(docs, l_tgt, docE);

    // 5) final FC -> [16,582]
    fc_kernel<<<B_SZ, 608>>>(fc1_w, fc1_b, fc2_w, fc2_b, out);
}

// round 6
// speedup vs baseline: 2.5569x; 1.0997x over previous
#include <cuda_runtime.h>
#include <cuda_fp16.h>
#include <cstdint>

// ---------------- constants ----------------
#define B_SZ   16
#define LINES  128
#define WPL    32
#define NLINE  (B_SZ*LINES)          // 2048
#define EMB_D  300
#define AD     400
#define HEADS  8
#define DPH    50
#define NCAT   1200                  // q|k|v concatenated
#define VOCAB  30000
#define INV_SQRT50 0.14142135623730951f
#define NEGPEN 1e7f

#define KPAD_W  320                  // word-proj K pad (300 -> 320)
#define KPAD_L  416                  // line-proj K pad (400 -> 416)

// ---------------- scratch (device globals; no allocation allowed) ----------------
__device__ float g_vproj[(long)VOCAB * NCAT]; // [30000][1200]
__device__ float g_lineE[NLINE * AD];          // [2048][400]
__device__ float g_lqkv[NLINE * NCAT];         // [2048][1200]
__device__ float g_docE[B_SZ * AD];            // [16][400]
__device__ __align__(16) __half g_WBhi[NCAT * KPAD_W];  // word weights [1200][320]
__device__ __align__(16) __half g_WBlo[NCAT * KPAD_W];
__device__ __align__(16) __half g_Ahi[(long)VOCAB * KPAD_W];  // emb [30000][320]
__device__ __align__(16) __half g_Alo[(long)VOCAB * KPAD_W];
__device__ __align__(16) __half g_LBhi[NCAT * KPAD_L];  // line weights [1200][416]
__device__ __align__(16) __half g_LBlo[NCAT * KPAD_L];
__device__ __align__(16) __half g_A2hi[NLINE * KPAD_L]; // lineE [2048][416]
__device__ __align__(16) __half g_A2lo[NLINE * KPAD_L];

// ---------------- PTX helpers (baseline ISA only) ----------------
__device__ __forceinline__ void cp16(void* dst, const void* src) {
    uint32_t d = (uint32_t)__cvta_generic_to_shared(dst);
    asm volatile("cp.async.ca.shared.global [%0], [%1], 16;" :: "r"(d), "l"(src));
}
__device__ __forceinline__ void cp_commit() {
    asm volatile("cp.async.commit_group;" ::: "memory");
}
template<int N>
__device__ __forceinline__ void cp_wait() {
    asm volatile("cp.async.wait_group %0;" :: "n"(N) : "memory");
}
__device__ __forceinline__ void mma16816(float* c, const uint32_t* a, const uint32_t* b) {
    asm volatile("mma.sync.aligned.m16n8k16.row.col.f32.f16.f16.f32 "
        "{%0,%1,%2,%3}, {%4,%5,%6,%7}, {%8,%9}, {%0,%1,%2,%3};"
        : "+f"(c[0]), "+f"(c[1]), "+f"(c[2]), "+f"(c[3])
        : "r"(a[0]), "r"(a[1]), "r"(a[2]), "r"(a[3]), "r"(b[0]), "r"(b[1]));
}
__device__ __forceinline__ uint32_t ld32s(const __half* p) {
    return *reinterpret_cast<const uint32_t*>(p);
}

// =====================================================================
// Prep: split weight trio [K][400]x3 -> hi/lo [1200 n][kpad] fp16
// =====================================================================
__global__ __launch_bounds__(256)
void splitW_kernel(const float* __restrict__ W0, const float* __restrict__ W1,
                   const float* __restrict__ W2, int K, int kpad,
                   __half* __restrict__ outHi, __half* __restrict__ outLo)
{
    int idx = blockIdx.x * 256 + threadIdx.x;
    if (idx >= NCAT * (kpad / 2)) return;
    int n  = idx / (kpad / 2);
    int k0 = (idx % (kpad / 2)) * 2;
    const float* W = (n < AD) ? W0 : (n < 2 * AD ? W1 : W2);
    int lc = (n < AD) ? n : (n < 2 * AD ? n - AD : n - 2 * AD);
    float x0 = (k0     < K) ? W[(long)k0 * AD + lc]       : 0.f;
    float x1 = (k0 + 1 < K) ? W[(long)(k0 + 1) * AD + lc] : 0.f;
    __half h0 = __float2half(x0), h1 = __float2half(x1);
    __half l0 = __float2half(x0 - __half2float(h0));
    __half l1 = __float2half(x1 - __half2float(h1));
    *reinterpret_cast<__half2*>(outHi + (long)n * kpad + k0) = __halves2half2(h0, h1);
    *reinterpret_cast<__half2*>(outLo + (long)n * kpad + k0) = __halves2half2(l0, l1);
}

// =====================================================================
// Prep: split row-major A [M][K] fp32 -> hi/lo [M][kpad] fp16
// =====================================================================
__global__ __launch_bounds__(256)
void splitA_kernel(const float* __restrict__ A, int M, int K, int kpad,
                   __half* __restrict__ outHi, __half* __restrict__ outLo)
{
    long idx = (long)blockIdx.x * 256 + threadIdx.x;
    if (idx >= (long)M * (kpad / 2)) return;
    int m  = (int)(idx / (kpad / 2));
    int k0 = (int)(idx % (kpad / 2)) * 2;
    float x0 = 0.f, x1 = 0.f;
    if (k0 + 1 < K) {
        float2 v = *reinterpret_cast<const float2*>(A + (long)m * K + k0);
        x0 = v.x; x1 = v.y;
    } else if (k0 < K) {
        x0 = A[(long)m * K + k0];
    }
    __half h0 = __float2half(x0), h1 = __float2half(x1);
    __half l0 = __float2half(x0 - __half2float(h0));
    __half l1 = __float2half(x1 - __half2float(h1));
    *reinterpret_cast<__half2*>(outHi + (long)m * kpad + k0) = __halves2half2(h0, h1);
    *reinterpret_cast<__half2*>(outLo + (long)m * kpad + k0) = __halves2half2(l0, l1);
}

// =====================================================================
// Generic streaming HMMA GEMM + bias + ELU (fp16 hi/lo 3-term):
//   out[M][1200] = elu(A @ B^T + bias),  A:[M][kpad], B:[1200][kpad]
// Tile M128 x N80, KC=32 double-buffered cp.async. 256 thr (8 warps: 4M x 2N),
// warp tile M32 x N40. grid = (ceil(M/128), 15).
// =====================================================================
#define GKC    32
#define GPITCH 40                       // halves per chunk-row (80B, conflict-free)
#define ABUF   (128 * GPITCH)           // 5120 halves
#define BBUF   (80 * GPITCH)            // 3200 halves
#define GEMM_SMEM ((4 * ABUF + 4 * BBUF) * 2)   // 66560 B

__global__ __launch_bounds__(256)
void gemm_elu_kernel(const __half* __restrict__ Ahi, const __half* __restrict__ Alo,
                     int M, int kpad, int nchunks,
                     const __half* __restrict__ Bhi, const __half* __restrict__ Blo,
                     const float* __restrict__ Bb0, const float* __restrict__ Bb1,
                     const float* __restrict__ Bb2,
                     float* __restrict__ out)
{
    extern __shared__ __half sh[];
    __half* sA = sh;                    // [buf][split][128][GPITCH]
    __half* sB = sh + 4 * ABUF;         // [buf][split][80][GPITCH]

    const int tid  = threadIdx.x;
    const int wid  = tid >> 5;
    const int lane = tid & 31;
    const int g4 = lane >> 2;
    const int l4 = lane & 3;
    const int wm = wid >> 1;            // 0..3 (M slab of 32)
    const int wn = wid & 1;             // 0..1 (N slab of 40)
    const int bx = blockIdx.x;
    const int nt = blockIdx.y;          // 0..14

    auto prefetch = [&](int c) {
        const int buf = c & 1;
        const long kbase = (long)c * GKC;
        // A: 128 rows x 4 segs x 2 splits = 1024 cp16
        #pragma unroll
        for (int it = 0; it < 4; it++) {
            int idx = tid + it * 256;
            int split = idx >> 9;
            int rem = idx & 511;
            int r = rem >> 2;
            int seg = rem & 3;
            int row = bx * 128 + r;
            if (row >= M) row = M - 1;
            const __half* src = (split ? Alo : Ahi) + (long)row * kpad + kbase + seg * 8;
            __half* dst = sA + (buf * 2 + split) * ABUF + r * GPITCH + seg * 8;
            cp16(dst, src);
        }
        // B: 80 rows x 4 segs x 2 splits = 640 cp16
        #pragma unroll
        for (int it = 0; it < 3; it++) {
            int idx = tid + it * 256;
            if (idx < 640) {
                int split = (idx >= 320) ? 1 : 0;
                int rem = idx - split * 320;
                int r = rem >> 2;
                int seg = rem & 3;
                const __half* src = (split ? Blo : Bhi)
                                  + (long)(nt * 80 + r) * kpad + kbase + seg * 8;
                __half* dst = sB + (buf * 2 + split) * BBUF + r * GPITCH + seg * 8;
                cp16(dst, src);
            }
        }
    };

    float acc[2][5][4];
    #pragma unroll
    for (int mi = 0; mi < 2; mi++)
        #pragma unroll
        for (int ni = 0; ni < 5; ni++)
            #pragma unroll
            for (int r = 0; r < 4; r++) acc[mi][ni][r] = 0.f;

    prefetch(0);
    cp_commit();

    for (int c = 0; c < nchunks; c++) {
        if (c + 1 < nchunks) { prefetch(c + 1); cp_commit(); cp_wait<1>(); }
        else                 { cp_wait<0>(); }
        __syncthreads();

        const int buf = c & 1;
        const __half* pAh = sA + (buf * 2 + 0) * ABUF + (wm * 32 + g4) * GPITCH;
        const __half* pAl = sA + (buf * 2 + 1) * ABUF + (wm * 32 + g4) * GPITCH;
        const __half* pBh = sB + (buf * 2 + 0) * BBUF + (wn * 40 + g4) * GPITCH;
        const __half* pBl = sB + (buf * 2 + 1) * BBUF + (wn * 40 + g4) * GPITCH;

        #pragma unroll
        for (int ks = 0; ks < 2; ks++) {
            const int kk = ks * 16 + l4 * 2;
            uint32_t ah[2][4], al[2][4];
            #pragma unroll
            for (int mi = 0; mi < 2; mi++) {
                const __half* p0 = pAh + mi * (16 * GPITCH);
                const __half* p1 = pAl + mi * (16 * GPITCH);
                ah[mi][0] = ld32s(p0 + kk);
                ah[mi][1] = ld32s(p0 + 8 * GPITCH + kk);
                ah[mi][2] = ld32s(p0 + kk + 8);
                ah[mi][3] = ld32s(p0 + 8 * GPITCH + kk + 8);
                al[mi][0] = ld32s(p1 + kk);
                al[mi][1] = ld32s(p1 + 8 * GPITCH + kk);
                al[mi][2] = ld32s(p1 + kk + 8);
                al[mi][3] = ld32s(p1 + 8 * GPITCH + kk + 8);
            }
            uint32_t bh[5][2], bl[5][2];
            #pragma unroll
            for (int ni = 0; ni < 5; ni++) {
                bh[ni][0] = ld32s(pBh + ni * (8 * GPITCH) + kk);
                bh[ni][1] = ld32s(pBh + ni * (8 * GPITCH) + kk + 8);
                bl[ni][0] = ld32s(pBl + ni * (8 * GPITCH) + kk);
                bl[ni][1] = ld32s(pBl + ni * (8 * GPITCH) + kk + 8);
            }
            #pragma unroll
            for (int mi = 0; mi < 2; mi++)
                #pragma unroll
                for (int ni = 0; ni < 5; ni++) {
                    mma16816(acc[mi][ni], ah[mi], bh[ni]);
                    mma16816(acc[mi][ni], ah[mi], bl[ni]);
                    mma16816(acc[mi][ni], al[mi], bh[ni]);
                }
        }
        __syncthreads();
    }

    // ---- epilogue: bias + ELU + guarded store ----
    const int sel = nt / 5;
    const float* Bb = (sel == 0) ? Bb0 : (sel == 1 ? Bb1 : Bb2);
    const int cb = nt * 80 - sel * AD;
    #pragma unroll
    for (int mi = 0; mi < 2; mi++) {
        #pragma unroll
        for (int r01 = 0; r01 < 2; r01++) {
            const int row = bx * 128 + wm * 32 + mi * 16 + g4 + r01 * 8;
            if (row < M) {
                #pragma unroll
                for (int ni = 0; ni < 5; ni++) {
                    int lc = cb + wn * 40 + ni * 8 + l4 * 2;
                    float x0 = acc[mi][ni][r01 * 2 + 0] + Bb[lc];
                    float x1 = acc[mi][ni][r01 * 2 + 1] + Bb[lc + 1];
                    float2 o;
                    o.x = (x0 > 0.f) ? x0 : expm1f(x0);
                    o.y = (x1 > 0.f) ? x1 : expm1f(x1);
                    int col = nt * 80 + wn * 40 + ni * 8 + l4 * 2;
                    *reinterpret_cast<float2*>(out + (long)row * NCAT + col) = o;
                }
            }
        }
    }
}

// =====================================================================
// Word-level attention + target attention.  One block per (line, head).
// =====================================================================
__global__ __launch_bounds__(128)
void watt_kernel(const int* __restrict__ docs, const float* __restrict__ w_tgt,
                 float* __restrict__ lineE)
{
    const int line = blockIdx.x;
    const int h    = blockIdx.y;
    const int tid  = threadIdx.x;

    __shared__ float q[WPL * DPH], k[WPL * DPH], v[WPL * DPH];
    __shared__ float ws[WPL * 33];
    __shared__ float watt[WPL * DPH];
    __shared__ float tw[WPL];
    __shared__ int   msk[WPL];
    __shared__ int   stok[WPL];

    if (tid < WPL) {
        int t = docs[line * WPL + tid];
        stok[tid] = t;
        msk[tid] = (t != 0);
    }
    __syncthreads();
    for (int i = tid; i < WPL * DPH; i += 128) {
        int w = i / DPH, d = i % DPH;
        long base = (long)stok[w] * NCAT + h * DPH + d;
        q[i] = g_vproj[base];
        k[i] = g_vproj[base + AD];
        v[i] = g_vproj[base + 2 * AD];
    }
    __syncthreads();

    {
        int i0 = (tid >> 3) * 2;
        int j0 = (tid & 7) * 4;
        float s0[4] = {0.f, 0.f, 0.f, 0.f};
        float s1[4] = {0.f, 0.f, 0.f, 0.f};
        for (int d = 0; d < DPH; d++) {
            float qa = q[i0 * DPH + d];
            float qb = q[(i0 + 1) * DPH + d];
            #pragma unroll
            for (int jj = 0; jj < 4; jj++) {
                float kv = k[(j0 + jj) * DPH + d];
                s0[jj] = fmaf(qa, kv, s0[jj]);
                s1[jj] = fmaf(qb, kv, s1[jj]);
            }
        }
        #pragma unroll
        for (int jj = 0; jj < 4; jj++) {
            float m = msk[j0 + jj] ? 0.f : NEGPEN;
            ws[i0 * 33 + j0 + jj]       = s0[jj] * INV_SQRT50 - m;
            ws[(i0 + 1) * 33 + j0 + jj] = s1[jj] * INV_SQRT50 - m;
        }
    }
    __syncthreads();

    {
        int wi = tid >> 5, ln = tid & 31;
        for (int r = wi; r < WPL; r += 4) {
            float x = ws[r * 33 + ln];
            float mx = x;
            #pragma unroll
            for (int o = 16; o; o >>= 1) mx = fmaxf(mx, __shfl_xor_sync(~0u, mx, o));
            float e = __expf(x - mx);
            float sm = e;
            #pragma unroll
            for (int o = 16; o; o >>= 1) sm += __shfl_xor_sync(~0u, sm, o);
            float wv = e / sm;
            if (!msk[r]) wv = 0.f;
            ws[r * 33 + ln] = wv;
        }
    }
    __syncthreads();

    for (int u = tid; u < (WPL / 2) * DPH; u += 128) {
        int ip = u / DPH, d = u % DPH;
        int i0 = ip * 2;
        float a0 = 0.f, a1 = 0.f;
        for (int j = 0; j < WPL; j++) {
            float vv = v[j * DPH + d];
            a0 = fmaf(ws[i0 * 33 + j], vv, a0);
            a1 = fmaf(ws[(i0 + 1) * 33 + j], vv, a1);
        }
        watt[i0 * DPH + d] = a0;
        watt[(i0 + 1) * DPH + d] = a1;
    }
    __syncthreads();

    if (tid < WPL) {
        int j = tid;
        float s = 0.f;
        for (int d = 0; d < DPH; d++)
            s = fmaf(w_tgt[h * DPH + d], k[j * DPH + d], s);
        s *= INV_SQRT50;
        if (!msk[j]) s -= NEGPEN;
        float mx = s;
        #pragma unroll
        for (int o = 16; o; o >>= 1) mx = fmaxf(mx, __shfl_xor_sync(~0u, mx, o));
        float e = __expf(s - mx);
        float sm = e;
        #pragma unroll
        for (int o = 16; o; o >>= 1) sm += __shfl_xor_sync(~0u, sm, o);
        tw[j] = e / sm;
    }
    __syncthreads();

    if (tid < DPH) {
        int d = tid;
        float a = 0.f;
        for (int j = 0; j < WPL; j++) a = fmaf(tw[j], watt[j * DPH + d], a);
        lineE[(long)line * AD + h * DPH + d] = a;
    }
}

// =====================================================================
// Line-level attention + doc target attention.  One block per (doc, head).
// =====================================================================
#define LA_Q  0
#define LA_K  (LINES * DPH)
#define LA_V  (2 * LINES * DPH)
#define LA_A  (3 * LINES * DPH)
#define LA_S  (4 * LINES * DPH)
#define LA_FLOATS (LA_S + LINES * 129)
#define LA_SMEM_BYTES (LA_FLOATS * 4)
#define LA_THREADS 512

__global__ __launch_bounds__(LA_THREADS)
void latt_kernel(const int* __restrict__ docs, const float* __restrict__ l_tgt,
                 float* __restrict__ docE)
{
    extern __shared__ float sm[];
    __shared__ int   mskL[LINES];
    __shared__ float ts[LINES];

    const int doc = blockIdx.x;
    const int h   = blockIdx.y;
    const int tid = threadIdx.x;

    if (tid < LINES) {
        int any = 0;
        const int* p = docs + (long)(doc * LINES + tid) * WPL;
        for (int w = 0; w < WPL; w++) any |= p[w];
        mskL[tid] = (any != 0);
    }
    for (int i = tid; i < LINES * DPH; i += LA_THREADS) {
        int l = i / DPH, d = i % DPH;
        long base = (long)(doc * LINES + l) * NCAT + h * DPH + d;
        sm[LA_Q + i] = g_lqkv[base];
        sm[LA_K + i] = g_lqkv[base + AD];
        sm[LA_V + i] = g_lqkv[base + 2 * AD];
    }
    __syncthreads();

    for (int u = tid; u < (LINES / 2) * (LINES / 4); u += LA_THREADS) {
        int ip = u >> 5;
        int jq = u & 31;
        int i0 = ip * 2, j0 = jq * 4;
        float s0[4] = {0.f, 0.f, 0.f, 0.f};
        float s1[4] = {0.f, 0.f, 0.f, 0.f};
        for (int d = 0; d < DPH; d++) {
            float qa = sm[LA_Q + i0 * DPH + d];
            float qb = sm[LA_Q + (i0 + 1) * DPH + d];
            #pragma unroll
            for (int jj = 0; jj < 4; jj++) {
                float kv = sm[LA_K + (j0 + jj) * DPH + d];
                s0[jj] = fmaf(qa, kv, s0[jj]);
                s1[jj] = fmaf(qb, kv, s1[jj]);
            }
        }
        #pragma unroll
        for (int jj = 0; jj < 4; jj++) {
            float m = mskL[j0 + jj] ? 0.f : NEGPEN;
            sm[LA_S + i0 * 129 + j0 + jj]       = s0[jj] * INV_SQRT50 - m;
            sm[LA_S + (i0 + 1) * 129 + j0 + jj] = s1[jj] * INV_SQRT50 - m;
        }
    }
    __syncthreads();

    {
        int wi = tid >> 5, ln = tid & 31;
        for (int r = wi; r < LINES; r += (LA_THREADS / 32)) {
            float x0 = sm[LA_S + r * 129 + ln];
            float x1 = sm[LA_S + r * 129 + ln + 32];
            float x2 = sm[LA_S + r * 129 + ln + 64];
            float x3 = sm[LA_S + r * 129 + ln + 96];
            float mx = fmaxf(fmaxf(x0, x1), fmaxf(x2, x3));
            #pragma unroll
            for (int o = 16; o; o >>= 1) mx = fmaxf(mx, __shfl_xor_sync(~0u, mx, o));
            float e0 = __expf(x0 - mx), e1 = __expf(x1 - mx);
            float e2 = __expf(x2 - mx), e3 = __expf(x3 - mx);
            float smv = e0 + e1 + e2 + e3;
            #pragma unroll
            for (int o = 16; o; o >>= 1) smv += __shfl_xor_sync(~0u, smv, o);
            float inv = (mskL[r] ? 1.f : 0.f) / smv;
            sm[LA_S + r * 129 + ln]      = e0 * inv;
            sm[LA_S + r * 129 + ln + 32] = e1 * inv;
            sm[LA_S + r * 129 + ln + 64] = e2 * inv;
            sm[LA_S + r * 129 + ln + 96] = e3 * inv;
        }
    }
    __syncthreads();

    for (int u = tid; u < (LINES / 2) * DPH; u += LA_THREADS) {
        int ip = u / DPH, d = u % DPH;
        int i0 = ip * 2;
        float a0 = 0.f, a1 = 0.f;
        for (int j = 0; j < LINES; j++) {
            float vv = sm[LA_V + j * DPH + d];
            a0 = fmaf(sm[LA_S + i0 * 129 + j], vv, a0);
            a1 = fmaf(sm[LA_S + (i0 + 1) * 129 + j], vv, a1);
        }
        sm[LA_A + i0 * DPH + d] = a0;
        sm[LA_A + (i0 + 1) * DPH + d] = a1;
    }
    __syncthreads();

    if (tid < LINES) {
        int j = tid;
        float s = 0.f;
        for (int d = 0; d < DPH; d++)
            s = fmaf(l_tgt[h * DPH + d], sm[LA_K + j * DPH + d], s);
        s *= INV_SQRT50;
        if (!mskL[j]) s -= NEGPEN;
        ts[j] = s;
    }
    __syncthreads();
    if (tid < 32) {
        int ln = tid;
        float x0 = ts[ln], x1 = ts[ln + 32], x2 = ts[ln + 64], x3 = ts[ln + 96];
        float mx = fmaxf(fmaxf(x0, x1), fmaxf(x2, x3));
        #pragma unroll
        for (int o = 16; o; o >>= 1) mx = fmaxf(mx, __shfl_xor_sync(~0u, mx, o));
        float e0 = __expf(x0 - mx), e1 = __expf(x1 - mx);
        float e2 = __expf(x2 - mx), e3 = __expf(x3 - mx);
        float smv = e0 + e1 + e2 + e3;
        #pragma unroll
        for (int o = 16; o; o >>= 1) smv += __shfl_xor_sync(~0u, smv, o);
        float inv = 1.f / smv;
        ts[ln] = e0 * inv; ts[ln + 32] = e1 * inv;
        ts[ln + 64] = e2 * inv; ts[ln + 96] = e3 * inv;
    }
    __syncthreads();
    if (tid < DPH) {
        int d = tid;
        float a = 0.f;
        for (int j = 0; j < LINES; j++) a = fmaf(ts[j], sm[LA_A + j * DPH + d], a);
        docE[(long)doc * AD + h * DPH + d] = a;
    }
}

// =====================================================================
// Final FC
// =====================================================================
__global__ __launch_bounds__(608)
void fc_kernel(const float* __restrict__ fc1w, const float* __restrict__ fc1b,
               const float* __restrict__ fc2w, const float* __restrict__ fc2b,
               float* __restrict__ out)
{
    const int b = blockIdx.x;
    const int tid = threadIdx.x;
    __shared__ float de[AD];
    for (int i = tid; i < AD; i += 608) de[i] = g_docE[b * AD + i];
    __syncthreads();
    if (tid < 582) {
        float a;
        if (tid < 70) {
            a = fc1b[tid];
            for (int kk = 0; kk < AD; kk++) a = fmaf(de[kk], fc1w[kk * 70 + tid], a);
        } else {
            int c = tid - 70;
            a = fc2b[c];
            for (int kk = 0; kk < AD; kk++) a = fmaf(de[kk], fc2w[kk * 512 + c], a);
        }
        out[b * 582 + tid] = a;
    }
}

// =====================================================================
extern "C" void kernel_launch(void* const* d_in, const int* in_sizes, int n_in,
                              void* d_out, int out_size)
{
    const int*   docs  = (const int*)  d_in[0];
    const float* emb   = (const float*)d_in[1];
    const float* wq_w  = (const float*)d_in[2];
    const float* wq_b  = (const float*)d_in[3];
    const float* wk_w  = (const float*)d_in[4];
    const float* wk_b  = (const float*)d_in[5];
    const float* wv_w  = (const float*)d_in[6];
    const float* wv_b  = (const float*)d_in[7];
    const float* w_tgt = (const float*)d_in[8];
    const float* lq_w  = (const float*)d_in[9];
    const float* lq_b  = (const float*)d_in[10];
    const float* lk_w  = (const float*)d_in[11];
    const float* lk_b  = (const float*)d_in[12];
    const float* lv_w  = (const float*)d_in[13];
    const float* lv_b  = (const float*)d_in[14];
    const float* l_tgt = (const float*)d_in[15];
    const float* fc1_w = (const float*)d_in[16];
    const float* fc1_b = (const float*)d_in[17];
    const float* fc2_w = (const float*)d_in[18];
    const float* fc2_b = (const float*)d_in[19];
    float* out = (float*)d_out;

    float *vproj, *lineE, *lqkv, *docE;
    __half *wbhi, *wblo, *ahi, *alo, *lbhi, *lblo, *a2hi, *a2lo;
    cudaGetSymbolAddress((void**)&vproj, g_vproj);
    cudaGetSymbolAddress((void**)&lineE, g_lineE);
    cudaGetSymbolAddress((void**)&lqkv,  g_lqkv);
    cudaGetSymbolAddress((void**)&docE,  g_docE);
    cudaGetSymbolAddress((void**)&wbhi,  g_WBhi);
    cudaGetSymbolAddress((void**)&wblo,  g_WBlo);
    cudaGetSymbolAddress((void**)&ahi,   g_Ahi);
    cudaGetSymbolAddress((void**)&alo,   g_Alo);
    cudaGetSymbolAddress((void**)&lbhi,  g_LBhi);
    cudaGetSymbolAddress((void**)&lblo,  g_LBlo);
    cudaGetSymbolAddress((void**)&a2hi,  g_A2hi);
    cudaGetSymbolAddress((void**)&a2lo,  g_A2lo);

    // 0) weight + emb splits (independent)
    splitW_kernel<<<(NCAT * (KPAD_W / 2) + 255) / 256, 256>>>(
        wq_w, wk_w, wv_w, EMB_D, KPAD_W, wbhi, wblo);
    splitW_kernel<<<(NCAT * (KPAD_L / 2) + 255) / 256, 256>>>(
        lq_w, lk_w, lv_w, AD, KPAD_L, lbhi, lblo);
    splitA_kernel<<<(int)(((long)VOCAB * (KPAD_W / 2) + 255) / 256), 256>>>(
        emb, VOCAB, EMB_D, KPAD_W, ahi, alo);

    // 1) vocab-wide word projection: [30000][320] x [1200][320]^T
    cudaFuncSetAttribute(gemm_elu_kernel, cudaFuncAttributeMaxDynamicSharedMemorySize,
                         GEMM_SMEM);
    gemm_elu_kernel<<<dim3((VOCAB + 127) / 128, 15), 256, GEMM_SMEM>>>(
        ahi, alo, VOCAB, KPAD_W, KPAD_W / GKC,
        wbhi, wblo, wq_b, wk_b, wv_b, vproj);

    // 2) word attention + target attention -> line_e [2048,400]
    watt_kernel<<<dim3(NLINE, HEADS), 128>>>(docs, w_tgt, lineE);

    // 3) line projection on the same HMMA kernel
    splitA_kernel<<<(NLINE * (KPAD_L / 2) + 255) / 256, 256>>>(
        lineE, NLINE, AD, KPAD_L, a2hi, a2lo);
    gemm_elu_kernel<<<dim3(NLINE / 128, 15), 256, GEMM_SMEM>>>(
        a2hi, a2lo, NLINE, KPAD_L, KPAD_L / GKC,
        lbhi, lblo, lq_b, lk_b, lv_b, lqkv);

    // 4) line attention + doc target attention -> doc_e [16,400]
    cudaFuncSetAttribute(latt_kernel, cudaFuncAttributeMaxDynamicSharedMemorySize,
                         LA_SMEM_BYTES);
    latt_kernel<<<dim3(B_SZ, HEADS), LA_THREADS, LA_SMEM_BYTES>>>(docs, l_tgt, docE);

    // 5) final FC -> [16,582]
    fc_kernel<<<B_SZ, 608>>>(fc1_w, fc1_b, fc2_w, fc2_b, out);
}